// round 5
// baseline (speedup 1.0000x reference)
#include <cuda_runtime.h>
#include <cuda_bf16.h>
#include <math.h>
#include <stdint.h>

// Problem constants
#define BB   4
#define SS   2048
#define HID  1024
#define NH   16
#define HD   64
#define MR   (BB*SS)   // 8192 rows

// Scratch (device globals; no allocations allowed)
__device__ float g_q [ (size_t)MR * HID ];
__device__ float g_kv[ (size_t)MR * 2 * HID ];
__device__ float g_ao[ (size_t)MR * HID ];
// Pre-split bf16 operands for attention, layout [b][h][s][64]
__device__ __nv_bfloat16 g_qh[(size_t)MR * HID];
__device__ __nv_bfloat16 g_ql[(size_t)MR * HID];
__device__ __nv_bfloat16 g_kh[(size_t)MR * HID];
__device__ __nv_bfloat16 g_kl[(size_t)MR * HID];
__device__ __nv_bfloat16 g_vh[(size_t)MR * HID];
__device__ __nv_bfloat16 g_vl[(size_t)MR * HID];
// Pre-split GEMM operands
__device__ __nv_bfloat16 g_xh [(size_t)MR * HID];
__device__ __nv_bfloat16 g_xl [(size_t)MR * HID];
__device__ __nv_bfloat16 g_aoh[(size_t)MR * HID];
__device__ __nv_bfloat16 g_aol[(size_t)MR * HID];
__device__ __nv_bfloat16 g_qwh[(size_t)HID * HID];
__device__ __nv_bfloat16 g_qwl[(size_t)HID * HID];
__device__ __nv_bfloat16 g_kvwh[(size_t)2 * HID * HID];
__device__ __nv_bfloat16 g_kvwl[(size_t)2 * HID * HID];
__device__ __nv_bfloat16 g_owh[(size_t)HID * HID];
__device__ __nv_bfloat16 g_owl[(size_t)HID * HID];

__device__ __forceinline__ uint32_t smem_u32(const void* p) {
    uint32_t a;
    asm("{ .reg .u64 t; cvta.to.shared.u64 t, %1; cvt.u32.u64 %0, t; }"
        : "=r"(a) : "l"(p));
    return a;
}

__device__ __forceinline__ void bf16_split2(float x, float y,
                                            uint32_t& hi, uint32_t& lo) {
    __nv_bfloat16 hx = __float2bfloat16(x);
    __nv_bfloat16 hy = __float2bfloat16(y);
    __nv_bfloat16 lx = __float2bfloat16(x - __bfloat162float(hx));
    __nv_bfloat16 ly = __float2bfloat16(y - __bfloat162float(hy));
    __nv_bfloat162 h; h.x = hx; h.y = hy;
    __nv_bfloat162 l; l.x = lx; l.y = ly;
    hi = *reinterpret_cast<uint32_t*>(&h);
    lo = *reinterpret_cast<uint32_t*>(&l);
}

#define LDM_X4(r0, r1, r2, r3, addr) \
    asm volatile("ldmatrix.sync.aligned.m8n8.x4.shared.b16 {%0,%1,%2,%3}, [%4];" \
                 : "=r"(r0), "=r"(r1), "=r"(r2), "=r"(r3) : "r"(addr))
#define LDM_X4T(r0, r1, r2, r3, addr) \
    asm volatile("ldmatrix.sync.aligned.m8n8.x4.trans.shared.b16 {%0,%1,%2,%3}, [%4];" \
                 : "=r"(r0), "=r"(r1), "=r"(r2), "=r"(r3) : "r"(addr))

#define MMA_BF16(d, a, b0v, b1v) \
    asm volatile("mma.sync.aligned.m16n8k16.row.col.f32.bf16.bf16.f32 " \
                 "{%0,%1,%2,%3}, {%4,%5,%6,%7}, {%8,%9}, {%0,%1,%2,%3};" \
                 : "+f"((d)[0]), "+f"((d)[1]), "+f"((d)[2]), "+f"((d)[3]) \
                 : "r"((a)[0]), "r"((a)[1]), "r"((a)[2]), "r"((a)[3]), \
                   "r"(b0v), "r"(b1v))

#define CP_ASYNC16(dst, src) \
    asm volatile("cp.async.cg.shared.global [%0], [%1], 16;" \
                 :: "r"(dst), "l"(src) : "memory")
#define CP_COMMIT() asm volatile("cp.async.commit_group;" ::: "memory")
#define CP_WAIT1()  asm volatile("cp.async.wait_group 1;" ::: "memory")
#define CP_WAIT0()  asm volatile("cp.async.wait_group 0;" ::: "memory")

// ============================================================================
// Split fp32 -> bf16 hi/lo (4 floats per thread)
// ============================================================================
__global__ __launch_bounds__(256)
void split_f32(const float* __restrict__ src, __nv_bfloat16* __restrict__ dh,
               __nv_bfloat16* __restrict__ dl, int n4)
{
    int i = blockIdx.x * blockDim.x + threadIdx.x;
    if (i >= n4) return;
    float4 v = *reinterpret_cast<const float4*>(src + (size_t)i * 4);
    uint32_t h0, l0, h1, l1;
    bf16_split2(v.x, v.y, h0, l0);
    bf16_split2(v.z, v.w, h1, l1);
    *reinterpret_cast<uint2*>(dh + (size_t)i * 4) = make_uint2(h0, h1);
    *reinterpret_cast<uint2*>(dl + (size_t)i * 4) = make_uint2(l0, l1);
}

// ============================================================================
// Pre-split 3xBF16 GEMM with cp.async double buffering.
// C[M,N] = A[M,K] @ W[N,K]^T + bias.  CTA 128x128, 8 warps (64m x 32n), KC=32.
// ============================================================================
#define KC    32
#define PITCH 40
#define GT_EL (128 * PITCH)          // elements per operand tile
#define GSTAGE_EL (4 * GT_EL)        // Ah, Al, Bh, Bl

__global__ __launch_bounds__(256, 2)
void gemm_pre(const __nv_bfloat16* __restrict__ Ah, const __nv_bfloat16* __restrict__ Al,
              const __nv_bfloat16* __restrict__ Wh, const __nv_bfloat16* __restrict__ Wl,
              const float* __restrict__ bias, float* __restrict__ C,
              int M, int N, int K)
{
    __shared__ __align__(16) __nv_bfloat16 sbuf[2 * GSTAGE_EL];

    const int tid  = threadIdx.x;
    const int wid  = tid >> 5;
    const int lane = tid & 31;
    const int row0 = blockIdx.y * 128;
    const int col0 = blockIdx.x * 128;
    const int wm   = (wid >> 2) * 64;
    const int wn   = (wid & 3) * 32;

    const uint32_t sb_u = smem_u32(sbuf);
    const __nv_bfloat16* srcs[4] = {
        Ah + (size_t)row0 * K, Al + (size_t)row0 * K,
        Wh + (size_t)col0 * K, Wl + (size_t)col0 * K };

    const int NS = K / KC;

    // issue one stage: 4 tiles x 128 rows x 32 cols (64B/row = 4x16B chunks)
    auto issue = [&](int s, int bsel) {
        const int k0 = s * KC;
        uint32_t base = sb_u + (uint32_t)bsel * GSTAGE_EL * 2u;
#pragma unroll
        for (int a = 0; a < 4; a++) {
#pragma unroll
            for (int t = 0; t < 2; t++) {
                int idx = tid + t * 256;        // 0..511 chunk id
                int r   = idx >> 2;
                int c   = (idx & 3) * 8;
                uint32_t dst = base + (uint32_t)(a * GT_EL + r * PITCH + c) * 2u;
                CP_ASYNC16(dst, srcs[a] + (size_t)r * K + k0 + c);
            }
        }
        CP_COMMIT();
    };

    issue(0, 0);
    issue(1, 1);

    const int a_row = lane & 15;
    const int a_k   = (lane >> 4) << 3;
    const int b_n   = (lane & 7) + ((lane >> 4) << 3);
    const int b_k   = lane & 8;

    float acc[4][4][4];
#pragma unroll
    for (int mt = 0; mt < 4; mt++)
#pragma unroll
        for (int nt = 0; nt < 4; nt++)
#pragma unroll
            for (int r = 0; r < 4; r++) acc[mt][nt][r] = 0.f;

    for (int s = 0; s < NS; s++) {
        if (s < NS - 1) { CP_WAIT1(); } else { CP_WAIT0(); }
        __syncthreads();

        const uint32_t bAh = sb_u + (uint32_t)((s & 1) * GSTAGE_EL) * 2u;
        const uint32_t bAl = bAh + (uint32_t)GT_EL * 2u;
        const uint32_t bBh = bAh + (uint32_t)(2 * GT_EL) * 2u;
        const uint32_t bBl = bAh + (uint32_t)(3 * GT_EL) * 2u;

#pragma unroll
        for (int kk = 0; kk < KC; kk += 16) {
            uint32_t bh[8], bl[8];
#pragma unroll
            for (int p = 0; p < 2; p++) {
                uint32_t off = (uint32_t)((wn + p * 16 + b_n) * PITCH + kk + b_k) * 2u;
                LDM_X4(bh[p*4+0], bh[p*4+1], bh[p*4+2], bh[p*4+3], bBh + off);
                LDM_X4(bl[p*4+0], bl[p*4+1], bl[p*4+2], bl[p*4+3], bBl + off);
            }
#pragma unroll
            for (int mt = 0; mt < 4; mt++) {
                uint32_t ah[4], al[4];
                uint32_t off = (uint32_t)((wm + mt * 16 + a_row) * PITCH + kk + a_k) * 2u;
                LDM_X4(ah[0], ah[1], ah[2], ah[3], bAh + off);
                LDM_X4(al[0], al[1], al[2], al[3], bAl + off);
#pragma unroll
                for (int nt = 0; nt < 4; nt++) {
                    int p = nt >> 1;
                    int o = (nt & 1) * 2;
                    MMA_BF16(acc[mt][nt], ah, bh[p*4+o], bh[p*4+o+1]);
                    MMA_BF16(acc[mt][nt], ah, bl[p*4+o], bl[p*4+o+1]);
                    MMA_BF16(acc[mt][nt], al, bh[p*4+o], bh[p*4+o+1]);
                }
            }
        }
        __syncthreads();
        if (s + 2 < NS) issue(s + 2, s & 1);
    }

    const int g  = lane >> 2;
    const int t2 = (lane & 3) * 2;
#pragma unroll
    for (int mt = 0; mt < 4; mt++) {
#pragma unroll
        for (int nt = 0; nt < 4; nt++) {
            int row = row0 + wm + mt * 16 + g;
            int col = col0 + wn + nt * 8 + t2;
            float bv0 = bias ? __ldg(&bias[col])     : 0.f;
            float bv1 = bias ? __ldg(&bias[col + 1]) : 0.f;
            *reinterpret_cast<float2*>(&C[(size_t)row * N + col]) =
                make_float2(acc[mt][nt][0] + bv0, acc[mt][nt][1] + bv1);
            *reinterpret_cast<float2*>(&C[(size_t)(row + 8) * N + col]) =
                make_float2(acc[mt][nt][2] + bv0, acc[mt][nt][3] + bv1);
        }
    }
}

// ============================================================================
// QK-norm + hi/lo bf16 split + head-major relayout (q, k, v)
// ============================================================================
__global__ __launch_bounds__(256)
void qknorm_split(const float* __restrict__ gq_gamma,
                  const float* __restrict__ gk_gamma)
{
    int warp = (blockIdx.x * blockDim.x + threadIdx.x) >> 5;
    int lane = threadIdx.x & 31;
    const int per = MR * NH;
    int seg = warp / per;
    int t   = warp - seg * per;
    int row = t >> 4;
    int h   = t & 15;
    int b   = row / SS;
    int s   = row - b * SS;

    const float* src;
    bool donorm = true;
    const float* gamma = gq_gamma;
    __nv_bfloat16 *dh, *dl;
    if (seg == 0) {
        src = g_q + (size_t)row * HID + h * HD;
        dh = g_qh; dl = g_ql;
    } else if (seg == 1) {
        src = g_kv + (size_t)row * (2 * HID) + h * HD;
        gamma = gk_gamma;
        dh = g_kh; dl = g_kl;
    } else {
        src = g_kv + (size_t)row * (2 * HID) + HID + h * HD;
        donorm = false;
        dh = g_vh; dl = g_vl;
    }

    float2 v = *reinterpret_cast<const float2*>(src + lane * 2);
    if (donorm) {
        float ss = v.x * v.x + v.y * v.y;
#pragma unroll
        for (int m = 16; m > 0; m >>= 1)
            ss += __shfl_xor_sync(0xffffffffu, ss, m);
        float inv = 8.0f / fmaxf(sqrtf(ss), 1e-12f);
        float2 g = *reinterpret_cast<const float2*>(gamma + h * HD + lane * 2);
        v.x *= inv * g.x;
        v.y *= inv * g.y;
    }
    uint32_t hi, lo;
    bf16_split2(v.x, v.y, hi, lo);
    size_t out = ((size_t)(b * NH + h) * SS + s) * HD + lane * 2;
    *reinterpret_cast<uint32_t*>(dh + out) = hi;
    *reinterpret_cast<uint32_t*>(dl + out) = lo;
}

// ============================================================================
// Tensor-core flash attention (3xbf16 QK and PV), cp.async double-buffered.
// (proven round-4 kernel, unchanged)
// ============================================================================
#define APITCH 72
#define QTILE_EL  (128 * APITCH)
#define KVARR_EL  (64 * APITCH)
#define BUF_EL    (4 * KVARR_EL)
#define ATT_SMEM  ((2 * QTILE_EL + 2 * BUF_EL) * 2)
#define NT        (SS / 64)

__global__ __launch_bounds__(256, 1)
void attn_mma(const __nv_bfloat16* __restrict__ qh, const __nv_bfloat16* __restrict__ ql,
              const __nv_bfloat16* __restrict__ kh, const __nv_bfloat16* __restrict__ kl,
              const __nv_bfloat16* __restrict__ vh, const __nv_bfloat16* __restrict__ vl,
              float* __restrict__ og)
{
    extern __shared__ __nv_bfloat16 sm[];
    __nv_bfloat16* Qh = sm;
    __nv_bfloat16* Ql = Qh + QTILE_EL;
    __nv_bfloat16* Bf = Ql + QTILE_EL;

    const int tid  = threadIdx.x;
    const int wid  = tid >> 5;
    const int lane = tid & 31;
    const int bh   = blockIdx.y;
    const int q0   = blockIdx.x * 128;
    const int wm   = wid * 16;
    const size_t bh_off = (size_t)bh * SS * HD;

    const __nv_bfloat16* srcs[4] = {kh + bh_off, kl + bh_off, vh + bh_off, vl + bh_off};
    const uint32_t buf_u[2] = { smem_u32(Bf), smem_u32(Bf + BUF_EL) };
    const uint32_t Qh_u = smem_u32(Qh);
    const uint32_t Ql_u = smem_u32(Ql);

    auto issue = [&](int kt, int bsel) {
#pragma unroll
        for (int i = 0; i < 8; i++) {
            const __nv_bfloat16* sp = srcs[i >> 1];
            int rem = ((i & 1) << 8) + tid;
            int r = rem >> 3;
            int c = (rem & 7) * 8;
            uint32_t dst = buf_u[bsel] + (uint32_t)((i >> 1) * KVARR_EL + r * APITCH + c) * 2u;
            CP_ASYNC16(dst, sp + (size_t)(kt * 64 + r) * HD + c);
        }
        CP_COMMIT();
    };

    issue(0, 0);
    issue(1, 1);

    {
        const __nv_bfloat16* qsrc[2] = {qh + bh_off, ql + bh_off};
        __nv_bfloat16* qdst[2] = {Qh, Ql};
#pragma unroll
        for (int i = 0; i < 8; i++) {
            int rem = ((i & 3) << 8) + tid;
            int r = rem >> 3;
            int c = (rem & 7) * 8;
            uint4 v = *reinterpret_cast<const uint4*>(
                qsrc[i >> 2] + (size_t)(q0 + r) * HD + c);
            *reinterpret_cast<uint4*>(qdst[i >> 2] + r * APITCH + c) = v;
        }
    }
    __syncthreads();

    const int a_row = lane & 15;
    const int a_k   = (lane >> 4) << 3;
    uint32_t qfh[4][4], qfl[4][4];
#pragma unroll
    for (int ks = 0; ks < 4; ks++) {
        uint32_t off = (uint32_t)((wm + a_row) * APITCH + ks * 16 + a_k) * 2u;
        LDM_X4(qfh[ks][0], qfh[ks][1], qfh[ks][2], qfh[ks][3], Qh_u + off);
        LDM_X4(qfl[ks][0], qfl[ks][1], qfl[ks][2], qfl[ks][3], Ql_u + off);
    }

    const int b_n = (lane & 7) + ((lane >> 4) << 3);
    const int b_k = lane & 8;

    float m0 = -1e30f, m1 = -1e30f, l0 = 0.f, l1 = 0.f;
    float O[8][4];
#pragma unroll
    for (int d = 0; d < 8; d++)
#pragma unroll
        for (int r = 0; r < 4; r++) O[d][r] = 0.f;

    for (int t = 0; t < NT; t++) {
        if (t < NT - 1) { CP_WAIT1(); } else { CP_WAIT0(); }
        __syncthreads();

        const uint32_t Ks_h = buf_u[t & 1];
        const uint32_t Ks_l = Ks_h + KVARR_EL * 2u;
        const uint32_t Vs_h = Ks_h + 2u * KVARR_EL * 2u;
        const uint32_t Vs_l = Ks_h + 3u * KVARR_EL * 2u;

        float S[8][4];
#pragma unroll
        for (int nt = 0; nt < 8; nt++)
#pragma unroll
            for (int r = 0; r < 4; r++) S[nt][r] = 0.f;

#pragma unroll
        for (int ks = 0; ks < 4; ks++) {
            uint32_t kfh[4][4], kfl[4][4];
#pragma unroll
            for (int p = 0; p < 4; p++) {
                uint32_t off = (uint32_t)((p * 16 + b_n) * APITCH + ks * 16 + b_k) * 2u;
                LDM_X4(kfh[p][0], kfh[p][1], kfh[p][2], kfh[p][3], Ks_h + off);
                LDM_X4(kfl[p][0], kfl[p][1], kfl[p][2], kfl[p][3], Ks_l + off);
            }
#pragma unroll
            for (int nt = 0; nt < 8; nt++) {
                int p = nt >> 1;
                int o = (nt & 1) * 2;
                MMA_BF16(S[nt], qfh[ks], kfh[p][o], kfh[p][o+1]);
                MMA_BF16(S[nt], qfh[ks], kfl[p][o], kfl[p][o+1]);
                MMA_BF16(S[nt], qfl[ks], kfh[p][o], kfh[p][o+1]);
            }
        }

        float mx0 = -1e30f, mx1 = -1e30f;
#pragma unroll
        for (int nt = 0; nt < 8; nt++) {
            mx0 = fmaxf(mx0, fmaxf(S[nt][0], S[nt][1]));
            mx1 = fmaxf(mx1, fmaxf(S[nt][2], S[nt][3]));
        }
        mx0 = fmaxf(mx0, __shfl_xor_sync(0xffffffffu, mx0, 1));
        mx0 = fmaxf(mx0, __shfl_xor_sync(0xffffffffu, mx0, 2));
        mx1 = fmaxf(mx1, __shfl_xor_sync(0xffffffffu, mx1, 1));
        mx1 = fmaxf(mx1, __shfl_xor_sync(0xffffffffu, mx1, 2));
        float mn0 = fmaxf(m0, mx0), mn1 = fmaxf(m1, mx1);
        float c0 = __expf(m0 - mn0), c1 = __expf(m1 - mn1);
        m0 = mn0; m1 = mn1;

        float s0 = 0.f, s1 = 0.f;
#pragma unroll
        for (int nt = 0; nt < 8; nt++) {
            S[nt][0] = __expf(S[nt][0] - m0);
            S[nt][1] = __expf(S[nt][1] - m0);
            S[nt][2] = __expf(S[nt][2] - m1);
            S[nt][3] = __expf(S[nt][3] - m1);
            s0 += S[nt][0] + S[nt][1];
            s1 += S[nt][2] + S[nt][3];
        }
        s0 += __shfl_xor_sync(0xffffffffu, s0, 1);
        s0 += __shfl_xor_sync(0xffffffffu, s0, 2);
        s1 += __shfl_xor_sync(0xffffffffu, s1, 1);
        s1 += __shfl_xor_sync(0xffffffffu, s1, 2);
        l0 = l0 * c0 + s0;
        l1 = l1 * c1 + s1;
#pragma unroll
        for (int d = 0; d < 8; d++) {
            O[d][0] *= c0; O[d][1] *= c0;
            O[d][2] *= c1; O[d][3] *= c1;
        }

        uint32_t pfh[4][4], pfl[4][4];
#pragma unroll
        for (int ks = 0; ks < 4; ks++) {
            bf16_split2(S[2*ks][0],   S[2*ks][1],   pfh[ks][0], pfl[ks][0]);
            bf16_split2(S[2*ks][2],   S[2*ks][3],   pfh[ks][1], pfl[ks][1]);
            bf16_split2(S[2*ks+1][0], S[2*ks+1][1], pfh[ks][2], pfl[ks][2]);
            bf16_split2(S[2*ks+1][2], S[2*ks+1][3], pfh[ks][3], pfl[ks][3]);
        }

#pragma unroll
        for (int ks = 0; ks < 4; ks++) {
            uint32_t vfh[4][4], vfl[4][4];
#pragma unroll
            for (int pd = 0; pd < 4; pd++) {
                uint32_t off = (uint32_t)((ks * 16 + (lane & 15)) * APITCH +
                                          pd * 16 + ((lane >> 4) << 3)) * 2u;
                LDM_X4T(vfh[pd][0], vfh[pd][1], vfh[pd][2], vfh[pd][3], Vs_h + off);
                LDM_X4T(vfl[pd][0], vfl[pd][1], vfl[pd][2], vfl[pd][3], Vs_l + off);
            }
#pragma unroll
            for (int dt = 0; dt < 8; dt++) {
                int pd = dt >> 1;
                int o  = (dt & 1) * 2;
                MMA_BF16(O[dt], pfh[ks], vfh[pd][o], vfh[pd][o+1]);
                MMA_BF16(O[dt], pfh[ks], vfl[pd][o], vfl[pd][o+1]);
                MMA_BF16(O[dt], pfl[ks], vfh[pd][o], vfh[pd][o+1]);
            }
        }

        __syncthreads();
        if (t + 2 < NT) issue(t + 2, t & 1);
    }

    const int g  = lane >> 2;
    const int t2 = (lane & 3) * 2;
    const int b  = bh >> 4;
    const int h  = bh & 15;
    float inv0 = 1.0f / l0, inv1 = 1.0f / l1;
    int row = b * SS + q0 + wm + g;
#pragma unroll
    for (int dt = 0; dt < 8; dt++) {
        int col = h * HD + dt * 8 + t2;
        *reinterpret_cast<float2*>(&og[(size_t)row * HID + col]) =
            make_float2(O[dt][0] * inv0, O[dt][1] * inv0);
        *reinterpret_cast<float2*>(&og[(size_t)(row + 8) * HID + col]) =
            make_float2(O[dt][2] * inv1, O[dt][3] * inv1);
    }
}

// ----------------------------------------------------------------------------
// Launch
// ----------------------------------------------------------------------------
extern "C" void kernel_launch(void* const* d_in, const int* in_sizes, int n_in,
                              void* d_out, int out_size)
{
    const float* x     = (const float*)d_in[0];
    const float* q_w   = (const float*)d_in[1];
    const float* q_b   = (const float*)d_in[2];
    const float* kv_w  = (const float*)d_in[3];
    const float* kv_b  = (const float*)d_in[4];
    const float* gq    = (const float*)d_in[5];
    const float* gk    = (const float*)d_in[6];
    const float* out_w = (const float*)d_in[7];
    float* out = (float*)d_out;

    float *pq, *pkv, *pao;
    cudaGetSymbolAddress((void**)&pq,  g_q);
    cudaGetSymbolAddress((void**)&pkv, g_kv);
    cudaGetSymbolAddress((void**)&pao, g_ao);
    __nv_bfloat16 *pqh, *pql, *pkh, *pkl, *pvh, *pvl;
    cudaGetSymbolAddress((void**)&pqh, g_qh);
    cudaGetSymbolAddress((void**)&pql, g_ql);
    cudaGetSymbolAddress((void**)&pkh, g_kh);
    cudaGetSymbolAddress((void**)&pkl, g_kl);
    cudaGetSymbolAddress((void**)&pvh, g_vh);
    cudaGetSymbolAddress((void**)&pvl, g_vl);
    __nv_bfloat16 *pxh, *pxl, *paoh, *paol, *pqwh, *pqwl, *pkvwh, *pkvwl, *powh, *powl;
    cudaGetSymbolAddress((void**)&pxh,   g_xh);
    cudaGetSymbolAddress((void**)&pxl,   g_xl);
    cudaGetSymbolAddress((void**)&paoh,  g_aoh);
    cudaGetSymbolAddress((void**)&paol,  g_aol);
    cudaGetSymbolAddress((void**)&pqwh,  g_qwh);
    cudaGetSymbolAddress((void**)&pqwl,  g_qwl);
    cudaGetSymbolAddress((void**)&pkvwh, g_kvwh);
    cudaGetSymbolAddress((void**)&pkvwl, g_kvwl);
    cudaGetSymbolAddress((void**)&powh,  g_owh);
    cudaGetSymbolAddress((void**)&powl,  g_owl);

    cudaFuncSetAttribute(attn_mma,
                         cudaFuncAttributeMaxDynamicSharedMemorySize, ATT_SMEM);

    // Pre-split inputs and weights
    {
        int n4 = MR * HID / 4;
        split_f32<<<(n4 + 255) / 256, 256>>>(x, pxh, pxl, n4);
        n4 = HID * HID / 4;
        split_f32<<<(n4 + 255) / 256, 256>>>(q_w, pqwh, pqwl, n4);
        n4 = 2 * HID * HID / 4;
        split_f32<<<(n4 + 255) / 256, 256>>>(kv_w, pkvwh, pkvwl, n4);
        n4 = HID * HID / 4;
        split_f32<<<(n4 + 255) / 256, 256>>>(out_w, powh, powl, n4);
    }
    // Q projection
    {
        dim3 grid(HID / 128, MR / 128);
        gemm_pre<<<grid, 256>>>(pxh, pxl, pqwh, pqwl, q_b, pq, MR, HID, HID);
    }
    // KV projection
    {
        dim3 grid((2 * HID) / 128, MR / 128);
        gemm_pre<<<grid, 256>>>(pxh, pxl, pkvwh, pkvwl, kv_b, pkv, MR, 2 * HID, HID);
    }
    // QK norm + split + relayout
    {
        int total_warps = 3 * MR * NH;
        qknorm_split<<<total_warps / 8, 256>>>(gq, gk);
    }
    // Attention (tensor cores)
    {
        dim3 grid(SS / 128, BB * NH);
        attn_mma<<<grid, 256, ATT_SMEM>>>(pqh, pql, pkh, pkl, pvh, pvl, pao);
    }
    // Split attention output, then output projection
    {
        int n4 = MR * HID / 4;
        split_f32<<<(n4 + 255) / 256, 256>>>(pao, paoh, paol, n4);
        dim3 grid(HID / 128, MR / 128);
        gemm_pre<<<grid, 256>>>(paoh, paol, powh, powl, nullptr, out, MR, HID, HID);
    }
}

// round 6
// speedup vs baseline: 1.0120x; 1.0120x over previous
#include <cuda_runtime.h>
#include <cuda_bf16.h>
#include <math.h>
#include <stdint.h>

// Problem constants
#define BB   4
#define SS   2048
#define HID  1024
#define NH   16
#define HD   64
#define MR   (BB*SS)   // 8192 rows

// Scratch (device globals; no allocations allowed)
__device__ float g_q [ (size_t)MR * HID ];
__device__ float g_kv[ (size_t)MR * 2 * HID ];
// Pre-split bf16 operands for attention, layout [b][h][s][64]
__device__ __nv_bfloat16 g_qh[(size_t)MR * HID];
__device__ __nv_bfloat16 g_ql[(size_t)MR * HID];
__device__ __nv_bfloat16 g_kh[(size_t)MR * HID];
__device__ __nv_bfloat16 g_kl[(size_t)MR * HID];
__device__ __nv_bfloat16 g_vh[(size_t)MR * HID];
__device__ __nv_bfloat16 g_vl[(size_t)MR * HID];
// Pre-split GEMM operands
__device__ __nv_bfloat16 g_xh [(size_t)MR * HID];
__device__ __nv_bfloat16 g_xl [(size_t)MR * HID];
__device__ __nv_bfloat16 g_aoh[(size_t)MR * HID];
__device__ __nv_bfloat16 g_aol[(size_t)MR * HID];
__device__ __nv_bfloat16 g_qwh[(size_t)HID * HID];
__device__ __nv_bfloat16 g_qwl[(size_t)HID * HID];
__device__ __nv_bfloat16 g_kvwh[(size_t)2 * HID * HID];
__device__ __nv_bfloat16 g_kvwl[(size_t)2 * HID * HID];
__device__ __nv_bfloat16 g_owh[(size_t)HID * HID];
__device__ __nv_bfloat16 g_owl[(size_t)HID * HID];

__device__ __forceinline__ uint32_t smem_u32(const void* p) {
    uint32_t a;
    asm("{ .reg .u64 t; cvta.to.shared.u64 t, %1; cvt.u32.u64 %0, t; }"
        : "=r"(a) : "l"(p));
    return a;
}

__device__ __forceinline__ void bf16_split2(float x, float y,
                                            uint32_t& hi, uint32_t& lo) {
    __nv_bfloat16 hx = __float2bfloat16(x);
    __nv_bfloat16 hy = __float2bfloat16(y);
    __nv_bfloat16 lx = __float2bfloat16(x - __bfloat162float(hx));
    __nv_bfloat16 ly = __float2bfloat16(y - __bfloat162float(hy));
    __nv_bfloat162 h; h.x = hx; h.y = hy;
    __nv_bfloat162 l; l.x = lx; l.y = ly;
    hi = *reinterpret_cast<uint32_t*>(&h);
    lo = *reinterpret_cast<uint32_t*>(&l);
}

#define LDM_X4(r0, r1, r2, r3, addr) \
    asm volatile("ldmatrix.sync.aligned.m8n8.x4.shared.b16 {%0,%1,%2,%3}, [%4];" \
                 : "=r"(r0), "=r"(r1), "=r"(r2), "=r"(r3) : "r"(addr))
#define LDM_X4T(r0, r1, r2, r3, addr) \
    asm volatile("ldmatrix.sync.aligned.m8n8.x4.trans.shared.b16 {%0,%1,%2,%3}, [%4];" \
                 : "=r"(r0), "=r"(r1), "=r"(r2), "=r"(r3) : "r"(addr))

#define MMA_BF16(d, a, b0v, b1v) \
    asm volatile("mma.sync.aligned.m16n8k16.row.col.f32.bf16.bf16.f32 " \
                 "{%0,%1,%2,%3}, {%4,%5,%6,%7}, {%8,%9}, {%0,%1,%2,%3};" \
                 : "+f"((d)[0]), "+f"((d)[1]), "+f"((d)[2]), "+f"((d)[3]) \
                 : "r"((a)[0]), "r"((a)[1]), "r"((a)[2]), "r"((a)[3]), \
                   "r"(b0v), "r"(b1v))

#define CP_ASYNC16(dst, src) \
    asm volatile("cp.async.cg.shared.global [%0], [%1], 16;" \
                 :: "r"(dst), "l"(src) : "memory")
#define CP_COMMIT() asm volatile("cp.async.commit_group;" ::: "memory")
#define CP_WAIT1()  asm volatile("cp.async.wait_group 1;" ::: "memory")
#define CP_WAIT0()  asm volatile("cp.async.wait_group 0;" ::: "memory")

// ============================================================================
// Split fp32 -> bf16 hi/lo (4 floats per thread)
// ============================================================================
__global__ __launch_bounds__(256)
void split_f32(const float* __restrict__ src, __nv_bfloat16* __restrict__ dh,
               __nv_bfloat16* __restrict__ dl, int n4)
{
    int i = blockIdx.x * blockDim.x + threadIdx.x;
    if (i >= n4) return;
    float4 v = *reinterpret_cast<const float4*>(src + (size_t)i * 4);
    uint32_t h0, l0, h1, l1;
    bf16_split2(v.x, v.y, h0, l0);
    bf16_split2(v.z, v.w, h1, l1);
    *reinterpret_cast<uint2*>(dh + (size_t)i * 4) = make_uint2(h0, h1);
    *reinterpret_cast<uint2*>(dl + (size_t)i * 4) = make_uint2(l0, l1);
}

// ============================================================================
// Pre-split 3xBF16 GEMM with cp.async double buffering (round-5 kernel).
// ============================================================================
#define KC    32
#define PITCH 40
#define GT_EL (128 * PITCH)
#define GSTAGE_EL (4 * GT_EL)

__global__ __launch_bounds__(256, 2)
void gemm_pre(const __nv_bfloat16* __restrict__ Ah, const __nv_bfloat16* __restrict__ Al,
              const __nv_bfloat16* __restrict__ Wh, const __nv_bfloat16* __restrict__ Wl,
              const float* __restrict__ bias, float* __restrict__ C,
              int M, int N, int K)
{
    __shared__ __align__(16) __nv_bfloat16 sbuf[2 * GSTAGE_EL];

    const int tid  = threadIdx.x;
    const int wid  = tid >> 5;
    const int lane = tid & 31;
    const int row0 = blockIdx.y * 128;
    const int col0 = blockIdx.x * 128;
    const int wm   = (wid >> 2) * 64;
    const int wn   = (wid & 3) * 32;

    const uint32_t sb_u = smem_u32(sbuf);
    const __nv_bfloat16* srcs[4] = {
        Ah + (size_t)row0 * K, Al + (size_t)row0 * K,
        Wh + (size_t)col0 * K, Wl + (size_t)col0 * K };

    const int NS = K / KC;

    auto issue = [&](int s, int bsel) {
        const int k0 = s * KC;
        uint32_t base = sb_u + (uint32_t)bsel * GSTAGE_EL * 2u;
#pragma unroll
        for (int a = 0; a < 4; a++) {
#pragma unroll
            for (int t = 0; t < 2; t++) {
                int idx = tid + t * 256;
                int r   = idx >> 2;
                int c   = (idx & 3) * 8;
                uint32_t dst = base + (uint32_t)(a * GT_EL + r * PITCH + c) * 2u;
                CP_ASYNC16(dst, srcs[a] + (size_t)r * K + k0 + c);
            }
        }
        CP_COMMIT();
    };

    issue(0, 0);
    issue(1, 1);

    const int a_row = lane & 15;
    const int a_k   = (lane >> 4) << 3;
    const int b_n   = (lane & 7) + ((lane >> 4) << 3);
    const int b_k   = lane & 8;

    float acc[4][4][4];
#pragma unroll
    for (int mt = 0; mt < 4; mt++)
#pragma unroll
        for (int nt = 0; nt < 4; nt++)
#pragma unroll
            for (int r = 0; r < 4; r++) acc[mt][nt][r] = 0.f;

    for (int s = 0; s < NS; s++) {
        if (s < NS - 1) { CP_WAIT1(); } else { CP_WAIT0(); }
        __syncthreads();

        const uint32_t bAh = sb_u + (uint32_t)((s & 1) * GSTAGE_EL) * 2u;
        const uint32_t bAl = bAh + (uint32_t)GT_EL * 2u;
        const uint32_t bBh = bAh + (uint32_t)(2 * GT_EL) * 2u;
        const uint32_t bBl = bAh + (uint32_t)(3 * GT_EL) * 2u;

#pragma unroll
        for (int kk = 0; kk < KC; kk += 16) {
            uint32_t bh[8], bl[8];
#pragma unroll
            for (int p = 0; p < 2; p++) {
                uint32_t off = (uint32_t)((wn + p * 16 + b_n) * PITCH + kk + b_k) * 2u;
                LDM_X4(bh[p*4+0], bh[p*4+1], bh[p*4+2], bh[p*4+3], bBh + off);
                LDM_X4(bl[p*4+0], bl[p*4+1], bl[p*4+2], bl[p*4+3], bBl + off);
            }
#pragma unroll
            for (int mt = 0; mt < 4; mt++) {
                uint32_t ah[4], al[4];
                uint32_t off = (uint32_t)((wm + mt * 16 + a_row) * PITCH + kk + a_k) * 2u;
                LDM_X4(ah[0], ah[1], ah[2], ah[3], bAh + off);
                LDM_X4(al[0], al[1], al[2], al[3], bAl + off);
#pragma unroll
                for (int nt = 0; nt < 4; nt++) {
                    int p = nt >> 1;
                    int o = (nt & 1) * 2;
                    MMA_BF16(acc[mt][nt], ah, bh[p*4+o], bh[p*4+o+1]);
                    MMA_BF16(acc[mt][nt], ah, bl[p*4+o], bl[p*4+o+1]);
                    MMA_BF16(acc[mt][nt], al, bh[p*4+o], bh[p*4+o+1]);
                }
            }
        }
        __syncthreads();
        if (s + 2 < NS) issue(s + 2, s & 1);
    }

    const int g  = lane >> 2;
    const int t2 = (lane & 3) * 2;
#pragma unroll
    for (int mt = 0; mt < 4; mt++) {
#pragma unroll
        for (int nt = 0; nt < 4; nt++) {
            int row = row0 + wm + mt * 16 + g;
            int col = col0 + wn + nt * 8 + t2;
            float bv0 = bias ? __ldg(&bias[col])     : 0.f;
            float bv1 = bias ? __ldg(&bias[col + 1]) : 0.f;
            *reinterpret_cast<float2*>(&C[(size_t)row * N + col]) =
                make_float2(acc[mt][nt][0] + bv0, acc[mt][nt][1] + bv1);
            *reinterpret_cast<float2*>(&C[(size_t)(row + 8) * N + col]) =
                make_float2(acc[mt][nt][2] + bv0, acc[mt][nt][3] + bv1);
        }
    }
}

// ============================================================================
// QK-norm + hi/lo bf16 split + head-major relayout (q, k, v)
// ============================================================================
__global__ __launch_bounds__(256)
void qknorm_split(const float* __restrict__ gq_gamma,
                  const float* __restrict__ gk_gamma)
{
    int warp = (blockIdx.x * blockDim.x + threadIdx.x) >> 5;
    int lane = threadIdx.x & 31;
    const int per = MR * NH;
    int seg = warp / per;
    int t   = warp - seg * per;
    int row = t >> 4;
    int h   = t & 15;
    int b   = row / SS;
    int s   = row - b * SS;

    const float* src;
    bool donorm = true;
    const float* gamma = gq_gamma;
    __nv_bfloat16 *dh, *dl;
    if (seg == 0) {
        src = g_q + (size_t)row * HID + h * HD;
        dh = g_qh; dl = g_ql;
    } else if (seg == 1) {
        src = g_kv + (size_t)row * (2 * HID) + h * HD;
        gamma = gk_gamma;
        dh = g_kh; dl = g_kl;
    } else {
        src = g_kv + (size_t)row * (2 * HID) + HID + h * HD;
        donorm = false;
        dh = g_vh; dl = g_vl;
    }

    float2 v = *reinterpret_cast<const float2*>(src + lane * 2);
    if (donorm) {
        float ss = v.x * v.x + v.y * v.y;
#pragma unroll
        for (int m = 16; m > 0; m >>= 1)
            ss += __shfl_xor_sync(0xffffffffu, ss, m);
        float inv = 8.0f / fmaxf(sqrtf(ss), 1e-12f);
        float2 g = *reinterpret_cast<const float2*>(gamma + h * HD + lane * 2);
        v.x *= inv * g.x;
        v.y *= inv * g.y;
    }
    uint32_t hi, lo;
    bf16_split2(v.x, v.y, hi, lo);
    size_t out = ((size_t)(b * NH + h) * SS + s) * HD + lane * 2;
    *reinterpret_cast<uint32_t*>(dh + out) = hi;
    *reinterpret_cast<uint32_t*>(dl + out) = lo;
}

// ============================================================================
// Tensor-core flash attention (3xbf16), 4 warps / 64 queries per CTA,
// 2 CTAs/SM so softmax of one CTA overlaps MMA of the other.
// Writes bf16 hi/lo output directly (fused split).
// ============================================================================
#define APITCH 72
#define QT_EL     (64 * APITCH)              // one Q operand tile (64 rows)
#define KVARR_EL  (64 * APITCH)
#define BUF_EL    (4 * KVARR_EL)
#define ATT_SMEM  ((2 * QT_EL + 2 * BUF_EL) * 2)   // 92160 bytes
#define NT        (SS / 64)

__global__ __launch_bounds__(128, 2)
void attn_mma(const __nv_bfloat16* __restrict__ qh, const __nv_bfloat16* __restrict__ ql,
              const __nv_bfloat16* __restrict__ kh, const __nv_bfloat16* __restrict__ kl,
              const __nv_bfloat16* __restrict__ vh, const __nv_bfloat16* __restrict__ vl,
              __nv_bfloat16* __restrict__ aoh, __nv_bfloat16* __restrict__ aol)
{
    extern __shared__ __nv_bfloat16 sm[];
    __nv_bfloat16* Qh = sm;
    __nv_bfloat16* Ql = Qh + QT_EL;
    __nv_bfloat16* Bf = Ql + QT_EL;

    const int tid  = threadIdx.x;
    const int wid  = tid >> 5;
    const int lane = tid & 31;
    const int bh   = blockIdx.y;
    const int q0   = blockIdx.x * 64;
    const int wm   = wid * 16;
    const size_t bh_off = (size_t)bh * SS * HD;

    const __nv_bfloat16* srcs[4] = {kh + bh_off, kl + bh_off, vh + bh_off, vl + bh_off};
    const uint32_t buf_u[2] = { smem_u32(Bf), smem_u32(Bf + BUF_EL) };
    const uint32_t Qh_u = smem_u32(Qh);
    const uint32_t Ql_u = smem_u32(Ql);

    // issue one 64-key KV stage: 4 arrays x 64 rows x 64 cols, 16B chunks
    auto issue = [&](int kt, int bsel) {
#pragma unroll
        for (int i = 0; i < 16; i++) {
            const __nv_bfloat16* sp = srcs[i >> 2];
            int rem = ((i & 3) << 7) + tid;
            int r = rem >> 3;
            int c = (rem & 7) * 8;
            uint32_t dst = buf_u[bsel] + (uint32_t)((i >> 2) * KVARR_EL + r * APITCH + c) * 2u;
            CP_ASYNC16(dst, sp + (size_t)(kt * 64 + r) * HD + c);
        }
        CP_COMMIT();
    };

    issue(0, 0);
    issue(1, 1);

    // Q tile (64 rows, hi/lo)
    {
        const __nv_bfloat16* qsrc[2] = {qh + bh_off, ql + bh_off};
        __nv_bfloat16* qdst[2] = {Qh, Ql};
#pragma unroll
        for (int i = 0; i < 8; i++) {
            int rem = ((i & 3) << 7) + tid;
            int r = rem >> 3;
            int c = (rem & 7) * 8;
            uint4 v = *reinterpret_cast<const uint4*>(
                qsrc[i >> 2] + (size_t)(q0 + r) * HD + c);
            *reinterpret_cast<uint4*>(qdst[i >> 2] + r * APITCH + c) = v;
        }
    }
    __syncthreads();

    const int a_row = lane & 15;
    const int a_k   = (lane >> 4) << 3;
    uint32_t qfh[4][4], qfl[4][4];
#pragma unroll
    for (int ks = 0; ks < 4; ks++) {
        uint32_t off = (uint32_t)((wm + a_row) * APITCH + ks * 16 + a_k) * 2u;
        LDM_X4(qfh[ks][0], qfh[ks][1], qfh[ks][2], qfh[ks][3], Qh_u + off);
        LDM_X4(qfl[ks][0], qfl[ks][1], qfl[ks][2], qfl[ks][3], Ql_u + off);
    }

    const int b_n = (lane & 7) + ((lane >> 4) << 3);
    const int b_k = lane & 8;

    float m0 = -1e30f, m1 = -1e30f, l0 = 0.f, l1 = 0.f;
    float O[8][4];
#pragma unroll
    for (int d = 0; d < 8; d++)
#pragma unroll
        for (int r = 0; r < 4; r++) O[d][r] = 0.f;

    for (int t = 0; t < NT; t++) {
        if (t < NT - 1) { CP_WAIT1(); } else { CP_WAIT0(); }
        __syncthreads();

        const uint32_t Ks_h = buf_u[t & 1];
        const uint32_t Ks_l = Ks_h + KVARR_EL * 2u;
        const uint32_t Vs_h = Ks_h + 2u * KVARR_EL * 2u;
        const uint32_t Vs_l = Ks_h + 3u * KVARR_EL * 2u;

        float S[8][4];
#pragma unroll
        for (int nt = 0; nt < 8; nt++)
#pragma unroll
            for (int r = 0; r < 4; r++) S[nt][r] = 0.f;

#pragma unroll
        for (int ks = 0; ks < 4; ks++) {
            uint32_t kfh[4][4], kfl[4][4];
#pragma unroll
            for (int p = 0; p < 4; p++) {
                uint32_t off = (uint32_t)((p * 16 + b_n) * APITCH + ks * 16 + b_k) * 2u;
                LDM_X4(kfh[p][0], kfh[p][1], kfh[p][2], kfh[p][3], Ks_h + off);
                LDM_X4(kfl[p][0], kfl[p][1], kfl[p][2], kfl[p][3], Ks_l + off);
            }
#pragma unroll
            for (int nt = 0; nt < 8; nt++) {
                int p = nt >> 1;
                int o = (nt & 1) * 2;
                MMA_BF16(S[nt], qfh[ks], kfh[p][o], kfh[p][o+1]);
                MMA_BF16(S[nt], qfh[ks], kfl[p][o], kfl[p][o+1]);
                MMA_BF16(S[nt], qfl[ks], kfh[p][o], kfh[p][o+1]);
            }
        }

        float mx0 = -1e30f, mx1 = -1e30f;
#pragma unroll
        for (int nt = 0; nt < 8; nt++) {
            mx0 = fmaxf(mx0, fmaxf(S[nt][0], S[nt][1]));
            mx1 = fmaxf(mx1, fmaxf(S[nt][2], S[nt][3]));
        }
        mx0 = fmaxf(mx0, __shfl_xor_sync(0xffffffffu, mx0, 1));
        mx0 = fmaxf(mx0, __shfl_xor_sync(0xffffffffu, mx0, 2));
        mx1 = fmaxf(mx1, __shfl_xor_sync(0xffffffffu, mx1, 1));
        mx1 = fmaxf(mx1, __shfl_xor_sync(0xffffffffu, mx1, 2));
        float mn0 = fmaxf(m0, mx0), mn1 = fmaxf(m1, mx1);
        float c0 = __expf(m0 - mn0), c1 = __expf(m1 - mn1);
        m0 = mn0; m1 = mn1;

        float s0 = 0.f, s1 = 0.f;
#pragma unroll
        for (int nt = 0; nt < 8; nt++) {
            S[nt][0] = __expf(S[nt][0] - m0);
            S[nt][1] = __expf(S[nt][1] - m0);
            S[nt][2] = __expf(S[nt][2] - m1);
            S[nt][3] = __expf(S[nt][3] - m1);
            s0 += S[nt][0] + S[nt][1];
            s1 += S[nt][2] + S[nt][3];
        }
        s0 += __shfl_xor_sync(0xffffffffu, s0, 1);
        s0 += __shfl_xor_sync(0xffffffffu, s0, 2);
        s1 += __shfl_xor_sync(0xffffffffu, s1, 1);
        s1 += __shfl_xor_sync(0xffffffffu, s1, 2);
        l0 = l0 * c0 + s0;
        l1 = l1 * c1 + s1;
#pragma unroll
        for (int d = 0; d < 8; d++) {
            O[d][0] *= c0; O[d][1] *= c0;
            O[d][2] *= c1; O[d][3] *= c1;
        }

        uint32_t pfh[4][4], pfl[4][4];
#pragma unroll
        for (int ks = 0; ks < 4; ks++) {
            bf16_split2(S[2*ks][0],   S[2*ks][1],   pfh[ks][0], pfl[ks][0]);
            bf16_split2(S[2*ks][2],   S[2*ks][3],   pfh[ks][1], pfl[ks][1]);
            bf16_split2(S[2*ks+1][0], S[2*ks+1][1], pfh[ks][2], pfl[ks][2]);
            bf16_split2(S[2*ks+1][2], S[2*ks+1][3], pfh[ks][3], pfl[ks][3]);
        }

#pragma unroll
        for (int ks = 0; ks < 4; ks++) {
            uint32_t vfh[4][4], vfl[4][4];
#pragma unroll
            for (int pd = 0; pd < 4; pd++) {
                uint32_t off = (uint32_t)((ks * 16 + (lane & 15)) * APITCH +
                                          pd * 16 + ((lane >> 4) << 3)) * 2u;
                LDM_X4T(vfh[pd][0], vfh[pd][1], vfh[pd][2], vfh[pd][3], Vs_h + off);
                LDM_X4T(vfl[pd][0], vfl[pd][1], vfl[pd][2], vfl[pd][3], Vs_l + off);
            }
#pragma unroll
            for (int dt = 0; dt < 8; dt++) {
                int pd = dt >> 1;
                int o  = (dt & 1) * 2;
                MMA_BF16(O[dt], pfh[ks], vfh[pd][o], vfh[pd][o+1]);
                MMA_BF16(O[dt], pfh[ks], vfl[pd][o], vfl[pd][o+1]);
                MMA_BF16(O[dt], pfl[ks], vfh[pd][o], vfh[pd][o+1]);
            }
        }

        __syncthreads();
        if (t + 2 < NT) issue(t + 2, t & 1);
    }

    // epilogue: write bf16 hi/lo of O/l directly (fused split), row-major [b*s][h*64+d]
    const int g  = lane >> 2;
    const int t2 = (lane & 3) * 2;
    const int b  = bh >> 4;
    const int h  = bh & 15;
    float inv0 = 1.0f / l0, inv1 = 1.0f / l1;
    int row = b * SS + q0 + wm + g;
#pragma unroll
    for (int dt = 0; dt < 8; dt++) {
        int col = h * HD + dt * 8 + t2;
        uint32_t hi, lo;
        bf16_split2(O[dt][0] * inv0, O[dt][1] * inv0, hi, lo);
        *reinterpret_cast<uint32_t*>(&aoh[(size_t)row * HID + col]) = hi;
        *reinterpret_cast<uint32_t*>(&aol[(size_t)row * HID + col]) = lo;
        bf16_split2(O[dt][2] * inv1, O[dt][3] * inv1, hi, lo);
        *reinterpret_cast<uint32_t*>(&aoh[(size_t)(row + 8) * HID + col]) = hi;
        *reinterpret_cast<uint32_t*>(&aol[(size_t)(row + 8) * HID + col]) = lo;
    }
}

// ----------------------------------------------------------------------------
// Launch
// ----------------------------------------------------------------------------
extern "C" void kernel_launch(void* const* d_in, const int* in_sizes, int n_in,
                              void* d_out, int out_size)
{
    const float* x     = (const float*)d_in[0];
    const float* q_w   = (const float*)d_in[1];
    const float* q_b   = (const float*)d_in[2];
    const float* kv_w  = (const float*)d_in[3];
    const float* kv_b  = (const float*)d_in[4];
    const float* gq    = (const float*)d_in[5];
    const float* gk    = (const float*)d_in[6];
    const float* out_w = (const float*)d_in[7];
    float* out = (float*)d_out;

    float *pq, *pkv;
    cudaGetSymbolAddress((void**)&pq,  g_q);
    cudaGetSymbolAddress((void**)&pkv, g_kv);
    __nv_bfloat16 *pqh, *pql, *pkh, *pkl, *pvh, *pvl;
    cudaGetSymbolAddress((void**)&pqh, g_qh);
    cudaGetSymbolAddress((void**)&pql, g_ql);
    cudaGetSymbolAddress((void**)&pkh, g_kh);
    cudaGetSymbolAddress((void**)&pkl, g_kl);
    cudaGetSymbolAddress((void**)&pvh, g_vh);
    cudaGetSymbolAddress((void**)&pvl, g_vl);
    __nv_bfloat16 *pxh, *pxl, *paoh, *paol, *pqwh, *pqwl, *pkvwh, *pkvwl, *powh, *powl;
    cudaGetSymbolAddress((void**)&pxh,   g_xh);
    cudaGetSymbolAddress((void**)&pxl,   g_xl);
    cudaGetSymbolAddress((void**)&paoh,  g_aoh);
    cudaGetSymbolAddress((void**)&paol,  g_aol);
    cudaGetSymbolAddress((void**)&pqwh,  g_qwh);
    cudaGetSymbolAddress((void**)&pqwl,  g_qwl);
    cudaGetSymbolAddress((void**)&pkvwh, g_kvwh);
    cudaGetSymbolAddress((void**)&pkvwl, g_kvwl);
    cudaGetSymbolAddress((void**)&powh,  g_owh);
    cudaGetSymbolAddress((void**)&powl,  g_owl);

    cudaFuncSetAttribute(attn_mma,
                         cudaFuncAttributeMaxDynamicSharedMemorySize, ATT_SMEM);

    // Pre-split inputs and weights
    {
        int n4 = MR * HID / 4;
        split_f32<<<(n4 + 255) / 256, 256>>>(x, pxh, pxl, n4);
        n4 = HID * HID / 4;
        split_f32<<<(n4 + 255) / 256, 256>>>(q_w, pqwh, pqwl, n4);
        n4 = 2 * HID * HID / 4;
        split_f32<<<(n4 + 255) / 256, 256>>>(kv_w, pkvwh, pkvwl, n4);
        n4 = HID * HID / 4;
        split_f32<<<(n4 + 255) / 256, 256>>>(out_w, powh, powl, n4);
    }
    // Q projection
    {
        dim3 grid(HID / 128, MR / 128);
        gemm_pre<<<grid, 256>>>(pxh, pxl, pqwh, pqwl, q_b, pq, MR, HID, HID);
    }
    // KV projection
    {
        dim3 grid((2 * HID) / 128, MR / 128);
        gemm_pre<<<grid, 256>>>(pxh, pxl, pkvwh, pkvwl, kv_b, pkv, MR, 2 * HID, HID);
    }
    // QK norm + split + relayout
    {
        int total_warps = 3 * MR * NH;
        qknorm_split<<<total_warps / 8, 256>>>(gq, gk);
    }
    // Attention (tensor cores, 64 queries/CTA, 2 CTAs/SM)
    {
        dim3 grid(SS / 64, BB * NH);    // (32, 64)
        attn_mma<<<grid, 128, ATT_SMEM>>>(pqh, pql, pkh, pkl, pvh, pvl, paoh, paol);
    }
    // Output projection (reads fused-split attention output)
    {
        dim3 grid(HID / 128, MR / 128);
        gemm_pre<<<grid, 256>>>(paoh, paol, powh, powl, nullptr, out, MR, HID, HID);
    }
}

// round 7
// speedup vs baseline: 1.0252x; 1.0131x over previous
#include <cuda_runtime.h>
#include <cuda_bf16.h>
#include <math.h>
#include <stdint.h>

// Problem constants
#define BB   4
#define SS   2048
#define HID  1024
#define NH   16
#define HD   64
#define MR   (BB*SS)   // 8192 rows

// Pre-split bf16 operands for attention, layout [b][h][s][64]
__device__ __nv_bfloat16 g_qh[(size_t)MR * HID];
__device__ __nv_bfloat16 g_ql[(size_t)MR * HID];
__device__ __nv_bfloat16 g_kh[(size_t)MR * HID];
__device__ __nv_bfloat16 g_kl[(size_t)MR * HID];
__device__ __nv_bfloat16 g_vh[(size_t)MR * HID];
__device__ __nv_bfloat16 g_vl[(size_t)MR * HID];
// Pre-split GEMM operands
__device__ __nv_bfloat16 g_xh [(size_t)MR * HID];
__device__ __nv_bfloat16 g_xl [(size_t)MR * HID];
__device__ __nv_bfloat16 g_aoh[(size_t)MR * HID];
__device__ __nv_bfloat16 g_aol[(size_t)MR * HID];
__device__ __nv_bfloat16 g_wh [(size_t)3 * HID * HID];   // concat(q_w, kv_w)
__device__ __nv_bfloat16 g_wl [(size_t)3 * HID * HID];
__device__ __nv_bfloat16 g_owh[(size_t)HID * HID];
__device__ __nv_bfloat16 g_owl[(size_t)HID * HID];

__device__ __forceinline__ uint32_t smem_u32(const void* p) {
    uint32_t a;
    asm("{ .reg .u64 t; cvta.to.shared.u64 t, %1; cvt.u32.u64 %0, t; }"
        : "=r"(a) : "l"(p));
    return a;
}

__device__ __forceinline__ void bf16_split2(float x, float y,
                                            uint32_t& hi, uint32_t& lo) {
    __nv_bfloat16 hx = __float2bfloat16(x);
    __nv_bfloat16 hy = __float2bfloat16(y);
    __nv_bfloat16 lx = __float2bfloat16(x - __bfloat162float(hx));
    __nv_bfloat16 ly = __float2bfloat16(y - __bfloat162float(hy));
    __nv_bfloat162 h; h.x = hx; h.y = hy;
    __nv_bfloat162 l; l.x = lx; l.y = ly;
    hi = *reinterpret_cast<uint32_t*>(&h);
    lo = *reinterpret_cast<uint32_t*>(&l);
}

#define LDM_X4(r0, r1, r2, r3, addr) \
    asm volatile("ldmatrix.sync.aligned.m8n8.x4.shared.b16 {%0,%1,%2,%3}, [%4];" \
                 : "=r"(r0), "=r"(r1), "=r"(r2), "=r"(r3) : "r"(addr))
#define LDM_X4T(r0, r1, r2, r3, addr) \
    asm volatile("ldmatrix.sync.aligned.m8n8.x4.trans.shared.b16 {%0,%1,%2,%3}, [%4];" \
                 : "=r"(r0), "=r"(r1), "=r"(r2), "=r"(r3) : "r"(addr))

#define MMA_BF16(d, a, b0v, b1v) \
    asm volatile("mma.sync.aligned.m16n8k16.row.col.f32.bf16.bf16.f32 " \
                 "{%0,%1,%2,%3}, {%4,%5,%6,%7}, {%8,%9}, {%0,%1,%2,%3};" \
                 : "+f"((d)[0]), "+f"((d)[1]), "+f"((d)[2]), "+f"((d)[3]) \
                 : "r"((a)[0]), "r"((a)[1]), "r"((a)[2]), "r"((a)[3]), \
                   "r"(b0v), "r"(b1v))

#define CP_ASYNC16(dst, src) \
    asm volatile("cp.async.cg.shared.global [%0], [%1], 16;" \
                 :: "r"(dst), "l"(src) : "memory")
#define CP_COMMIT() asm volatile("cp.async.commit_group;" ::: "memory")
#define CP_WAIT1()  asm volatile("cp.async.wait_group 1;" ::: "memory")
#define CP_WAIT0()  asm volatile("cp.async.wait_group 0;" ::: "memory")

// ============================================================================
// Split fp32 -> bf16 hi/lo
// ============================================================================
__global__ __launch_bounds__(256)
void split_f32(const float* __restrict__ src, __nv_bfloat16* __restrict__ dh,
               __nv_bfloat16* __restrict__ dl, int n4)
{
    int i = blockIdx.x * blockDim.x + threadIdx.x;
    if (i >= n4) return;
    float4 v = *reinterpret_cast<const float4*>(src + (size_t)i * 4);
    uint32_t h0, l0, h1, l1;
    bf16_split2(v.x, v.y, h0, l0);
    bf16_split2(v.z, v.w, h1, l1);
    *reinterpret_cast<uint2*>(dh + (size_t)i * 4) = make_uint2(h0, h1);
    *reinterpret_cast<uint2*>(dl + (size_t)i * 4) = make_uint2(l0, l1);
}

// ============================================================================
// Shared GEMM mainloop pieces
// ============================================================================
#define KC    32
#define PITCH 40
#define GT_EL (128 * PITCH)
#define GSTAGE_EL (4 * GT_EL)

// ============================================================================
// Merged QKV GEMM + fused qknorm/split/relayout epilogue.
// C[8192, 3072] = x @ concat(q_w,kv_w)^T + bias; per 128x128 tile the
// epilogue normalizes Q/K heads and writes bf16 hi/lo to [b][h][s][d].
// ============================================================================
__global__ __launch_bounds__(256, 2)
void gemm_qkv(const __nv_bfloat16* __restrict__ Ah, const __nv_bfloat16* __restrict__ Al,
              const __nv_bfloat16* __restrict__ Wh, const __nv_bfloat16* __restrict__ Wl,
              const float* __restrict__ q_b, const float* __restrict__ kv_b,
              const float* __restrict__ gq, const float* __restrict__ gk)
{
    __shared__ __align__(16) __nv_bfloat16 sbuf[2 * GSTAGE_EL];
    __shared__ float part[128][4];

    const int K = HID;
    const int tid  = threadIdx.x;
    const int wid  = tid >> 5;
    const int lane = tid & 31;
    const int row0 = blockIdx.y * 128;
    const int col0 = blockIdx.x * 128;
    const int wm   = (wid >> 2) * 64;
    const int wn   = (wid & 3) * 32;

    const uint32_t sb_u = smem_u32(sbuf);
    const __nv_bfloat16* srcs[4] = {
        Ah + (size_t)row0 * K, Al + (size_t)row0 * K,
        Wh + (size_t)col0 * K, Wl + (size_t)col0 * K };

    const int NS = K / KC;

    auto issue = [&](int s, int bsel) {
        const int k0 = s * KC;
        uint32_t base = sb_u + (uint32_t)bsel * GSTAGE_EL * 2u;
#pragma unroll
        for (int a = 0; a < 4; a++) {
#pragma unroll
            for (int t = 0; t < 2; t++) {
                int idx = tid + t * 256;
                int r   = idx >> 2;
                int c   = (idx & 3) * 8;
                uint32_t dst = base + (uint32_t)(a * GT_EL + r * PITCH + c) * 2u;
                CP_ASYNC16(dst, srcs[a] + (size_t)r * K + k0 + c);
            }
        }
        CP_COMMIT();
    };

    issue(0, 0);
    issue(1, 1);

    const int a_row = lane & 15;
    const int a_k   = (lane >> 4) << 3;
    const int b_n   = (lane & 7) + ((lane >> 4) << 3);
    const int b_k   = lane & 8;

    float acc[4][4][4];
#pragma unroll
    for (int mt = 0; mt < 4; mt++)
#pragma unroll
        for (int nt = 0; nt < 4; nt++)
#pragma unroll
            for (int r = 0; r < 4; r++) acc[mt][nt][r] = 0.f;

    for (int s = 0; s < NS; s++) {
        if (s < NS - 1) { CP_WAIT1(); } else { CP_WAIT0(); }
        __syncthreads();

        const uint32_t bAh = sb_u + (uint32_t)((s & 1) * GSTAGE_EL) * 2u;
        const uint32_t bAl = bAh + (uint32_t)GT_EL * 2u;
        const uint32_t bBh = bAh + (uint32_t)(2 * GT_EL) * 2u;
        const uint32_t bBl = bAh + (uint32_t)(3 * GT_EL) * 2u;

#pragma unroll
        for (int kk = 0; kk < KC; kk += 16) {
            uint32_t bh[8], bl[8];
#pragma unroll
            for (int p = 0; p < 2; p++) {
                uint32_t off = (uint32_t)((wn + p * 16 + b_n) * PITCH + kk + b_k) * 2u;
                LDM_X4(bh[p*4+0], bh[p*4+1], bh[p*4+2], bh[p*4+3], bBh + off);
                LDM_X4(bl[p*4+0], bl[p*4+1], bl[p*4+2], bl[p*4+3], bBl + off);
            }
#pragma unroll
            for (int mt = 0; mt < 4; mt++) {
                uint32_t ah[4], al[4];
                uint32_t off = (uint32_t)((wm + mt * 16 + a_row) * PITCH + kk + a_k) * 2u;
                LDM_X4(ah[0], ah[1], ah[2], ah[3], bAh + off);
                LDM_X4(al[0], al[1], al[2], al[3], bAl + off);
#pragma unroll
                for (int nt = 0; nt < 4; nt++) {
                    int p = nt >> 1;
                    int o = (nt & 1) * 2;
                    MMA_BF16(acc[mt][nt], ah, bh[p*4+o], bh[p*4+o+1]);
                    MMA_BF16(acc[mt][nt], ah, bl[p*4+o], bl[p*4+o+1]);
                    MMA_BF16(acc[mt][nt], al, bh[p*4+o], bh[p*4+o+1]);
                }
            }
        }
        __syncthreads();
        if (s + 2 < NS) issue(s + 2, s & 1);
    }

    // ---- fused epilogue ----
    const int g  = lane >> 2;
    const int t2 = (lane & 3) * 2;

    // bias add (before norm, per reference)
#pragma unroll
    for (int nt = 0; nt < 4; nt++) {
        int col = col0 + wn + nt * 8 + t2;
        float b0 = (col < HID) ? __ldg(&q_b[col])     : __ldg(&kv_b[col - HID]);
        float b1 = (col + 1 < HID) ? __ldg(&q_b[col + 1]) : __ldg(&kv_b[col + 1 - HID]);
#pragma unroll
        for (int mt = 0; mt < 4; mt++) {
            acc[mt][nt][0] += b0; acc[mt][nt][1] += b1;
            acc[mt][nt][2] += b0; acc[mt][nt][3] += b1;
        }
    }

    // per-warp partial sum of squares over this warp's 32 columns
#pragma unroll
    for (int mt = 0; mt < 4; mt++) {
#pragma unroll
        for (int rh = 0; rh < 2; rh++) {
            float ssum = 0.f;
#pragma unroll
            for (int nt = 0; nt < 4; nt++) {
                float v0 = acc[mt][nt][rh * 2 + 0];
                float v1 = acc[mt][nt][rh * 2 + 1];
                ssum += v0 * v0 + v1 * v1;
            }
            ssum += __shfl_xor_sync(0xffffffffu, ssum, 1);
            ssum += __shfl_xor_sync(0xffffffffu, ssum, 2);
            if ((lane & 3) == 0)
                part[wm + mt * 16 + g + rh * 8][wn >> 5] = ssum;
        }
    }
    __syncthreads();

    // seg: whole tile is within one of q / k / v (boundaries multiple of 128)
    const int seg = (col0 < HID) ? 0 : (col0 < 2 * HID) ? 1 : 2;
    const int h   = ((col0 & (HID - 1)) + wn) >> 6;   // head: constant per warp
    const int hl2 = (wn >> 5) & ~1;                    // 2*head-local
    __nv_bfloat16* dh = (seg == 0) ? g_qh : (seg == 1) ? g_kh : g_vh;
    __nv_bfloat16* dl = (seg == 0) ? g_ql : (seg == 1) ? g_kl : g_vl;
    const float* gamma = (seg == 0) ? gq : gk;

#pragma unroll
    for (int mt = 0; mt < 4; mt++) {
#pragma unroll
        for (int rh = 0; rh < 2; rh++) {
            int rloc = wm + mt * 16 + g + rh * 8;
            int row  = row0 + rloc;
            int b    = row >> 11;
            int srow = row & (SS - 1);
            float inv = 1.0f;
            if (seg < 2) {
                float hs = part[rloc][hl2] + part[rloc][hl2 + 1];
                inv = 8.0f / fmaxf(sqrtf(hs), 1e-12f);
            }
            size_t base = ((size_t)(b * NH + h) * SS + srow) * HD;
#pragma unroll
            for (int nt = 0; nt < 4; nt++) {
                int d = ((wn + nt * 8 + t2) & 63);
                float g0 = 1.f, g1 = 1.f;
                if (seg < 2) {
                    g0 = __ldg(&gamma[h * HD + d]);
                    g1 = __ldg(&gamma[h * HD + d + 1]);
                }
                float v0 = acc[mt][nt][rh * 2 + 0] * inv * g0;
                float v1 = acc[mt][nt][rh * 2 + 1] * inv * g1;
                uint32_t hi, lo;
                bf16_split2(v0, v1, hi, lo);
                *reinterpret_cast<uint32_t*>(&dh[base + d]) = hi;
                *reinterpret_cast<uint32_t*>(&dl[base + d]) = lo;
            }
        }
    }
}

// ============================================================================
// Pre-split 3xBF16 GEMM (out_proj): C = A @ W^T, fp32 out. (proven kernel)
// ============================================================================
__global__ __launch_bounds__(256, 2)
void gemm_pre(const __nv_bfloat16* __restrict__ Ah, const __nv_bfloat16* __restrict__ Al,
              const __nv_bfloat16* __restrict__ Wh, const __nv_bfloat16* __restrict__ Wl,
              float* __restrict__ C, int M, int N, int K)
{
    __shared__ __align__(16) __nv_bfloat16 sbuf[2 * GSTAGE_EL];

    const int tid  = threadIdx.x;
    const int wid  = tid >> 5;
    const int lane = tid & 31;
    const int row0 = blockIdx.y * 128;
    const int col0 = blockIdx.x * 128;
    const int wm   = (wid >> 2) * 64;
    const int wn   = (wid & 3) * 32;

    const uint32_t sb_u = smem_u32(sbuf);
    const __nv_bfloat16* srcs[4] = {
        Ah + (size_t)row0 * K, Al + (size_t)row0 * K,
        Wh + (size_t)col0 * K, Wl + (size_t)col0 * K };

    const int NS = K / KC;

    auto issue = [&](int s, int bsel) {
        const int k0 = s * KC;
        uint32_t base = sb_u + (uint32_t)bsel * GSTAGE_EL * 2u;
#pragma unroll
        for (int a = 0; a < 4; a++) {
#pragma unroll
            for (int t = 0; t < 2; t++) {
                int idx = tid + t * 256;
                int r   = idx >> 2;
                int c   = (idx & 3) * 8;
                uint32_t dst = base + (uint32_t)(a * GT_EL + r * PITCH + c) * 2u;
                CP_ASYNC16(dst, srcs[a] + (size_t)r * K + k0 + c);
            }
        }
        CP_COMMIT();
    };

    issue(0, 0);
    issue(1, 1);

    const int a_row = lane & 15;
    const int a_k   = (lane >> 4) << 3;
    const int b_n   = (lane & 7) + ((lane >> 4) << 3);
    const int b_k   = lane & 8;

    float acc[4][4][4];
#pragma unroll
    for (int mt = 0; mt < 4; mt++)
#pragma unroll
        for (int nt = 0; nt < 4; nt++)
#pragma unroll
            for (int r = 0; r < 4; r++) acc[mt][nt][r] = 0.f;

    for (int s = 0; s < NS; s++) {
        if (s < NS - 1) { CP_WAIT1(); } else { CP_WAIT0(); }
        __syncthreads();

        const uint32_t bAh = sb_u + (uint32_t)((s & 1) * GSTAGE_EL) * 2u;
        const uint32_t bAl = bAh + (uint32_t)GT_EL * 2u;
        const uint32_t bBh = bAh + (uint32_t)(2 * GT_EL) * 2u;
        const uint32_t bBl = bAh + (uint32_t)(3 * GT_EL) * 2u;

#pragma unroll
        for (int kk = 0; kk < KC; kk += 16) {
            uint32_t bh[8], bl[8];
#pragma unroll
            for (int p = 0; p < 2; p++) {
                uint32_t off = (uint32_t)((wn + p * 16 + b_n) * PITCH + kk + b_k) * 2u;
                LDM_X4(bh[p*4+0], bh[p*4+1], bh[p*4+2], bh[p*4+3], bBh + off);
                LDM_X4(bl[p*4+0], bl[p*4+1], bl[p*4+2], bl[p*4+3], bBl + off);
            }
#pragma unroll
            for (int mt = 0; mt < 4; mt++) {
                uint32_t ah[4], al[4];
                uint32_t off = (uint32_t)((wm + mt * 16 + a_row) * PITCH + kk + a_k) * 2u;
                LDM_X4(ah[0], ah[1], ah[2], ah[3], bAh + off);
                LDM_X4(al[0], al[1], al[2], al[3], bAl + off);
#pragma unroll
                for (int nt = 0; nt < 4; nt++) {
                    int p = nt >> 1;
                    int o = (nt & 1) * 2;
                    MMA_BF16(acc[mt][nt], ah, bh[p*4+o], bh[p*4+o+1]);
                    MMA_BF16(acc[mt][nt], ah, bl[p*4+o], bl[p*4+o+1]);
                    MMA_BF16(acc[mt][nt], al, bh[p*4+o], bh[p*4+o+1]);
                }
            }
        }
        __syncthreads();
        if (s + 2 < NS) issue(s + 2, s & 1);
    }

    const int g  = lane >> 2;
    const int t2 = (lane & 3) * 2;
#pragma unroll
    for (int mt = 0; mt < 4; mt++) {
#pragma unroll
        for (int nt = 0; nt < 4; nt++) {
            int row = row0 + wm + mt * 16 + g;
            int col = col0 + wn + nt * 8 + t2;
            *reinterpret_cast<float2*>(&C[(size_t)row * N + col]) =
                make_float2(acc[mt][nt][0], acc[mt][nt][1]);
            *reinterpret_cast<float2*>(&C[(size_t)(row + 8) * N + col]) =
                make_float2(acc[mt][nt][2], acc[mt][nt][3]);
        }
    }
}

// ============================================================================
// Tensor-core flash attention (3xbf16), 8 warps / 128 queries per CTA
// (proven round-4 mainloop), fused bf16 hi/lo output epilogue.
// ============================================================================
#define APITCH 72
#define QTILE_EL  (128 * APITCH)
#define KVARR_EL  (64 * APITCH)
#define BUF_EL    (4 * KVARR_EL)
#define ATT_SMEM  ((2 * QTILE_EL + 2 * BUF_EL) * 2)
#define NT        (SS / 64)

__global__ __launch_bounds__(256, 1)
void attn_mma(const __nv_bfloat16* __restrict__ qh, const __nv_bfloat16* __restrict__ ql,
              const __nv_bfloat16* __restrict__ kh, const __nv_bfloat16* __restrict__ kl,
              const __nv_bfloat16* __restrict__ vh, const __nv_bfloat16* __restrict__ vl,
              __nv_bfloat16* __restrict__ aoh, __nv_bfloat16* __restrict__ aol)
{
    extern __shared__ __nv_bfloat16 sm[];
    __nv_bfloat16* Qh = sm;
    __nv_bfloat16* Ql = Qh + QTILE_EL;
    __nv_bfloat16* Bf = Ql + QTILE_EL;

    const int tid  = threadIdx.x;
    const int wid  = tid >> 5;
    const int lane = tid & 31;
    const int bh   = blockIdx.y;
    const int q0   = blockIdx.x * 128;
    const int wm   = wid * 16;
    const size_t bh_off = (size_t)bh * SS * HD;

    const __nv_bfloat16* srcs[4] = {kh + bh_off, kl + bh_off, vh + bh_off, vl + bh_off};
    const uint32_t buf_u[2] = { smem_u32(Bf), smem_u32(Bf + BUF_EL) };
    const uint32_t Qh_u = smem_u32(Qh);
    const uint32_t Ql_u = smem_u32(Ql);

    auto issue = [&](int kt, int bsel) {
#pragma unroll
        for (int i = 0; i < 8; i++) {
            const __nv_bfloat16* sp = srcs[i >> 1];
            int rem = ((i & 1) << 8) + tid;
            int r = rem >> 3;
            int c = (rem & 7) * 8;
            uint32_t dst = buf_u[bsel] + (uint32_t)((i >> 1) * KVARR_EL + r * APITCH + c) * 2u;
            CP_ASYNC16(dst, sp + (size_t)(kt * 64 + r) * HD + c);
        }
        CP_COMMIT();
    };

    issue(0, 0);
    issue(1, 1);

    {
        const __nv_bfloat16* qsrc[2] = {qh + bh_off, ql + bh_off};
        __nv_bfloat16* qdst[2] = {Qh, Ql};
#pragma unroll
        for (int i = 0; i < 8; i++) {
            int rem = ((i & 3) << 8) + tid;
            int r = rem >> 3;
            int c = (rem & 7) * 8;
            uint4 v = *reinterpret_cast<const uint4*>(
                qsrc[i >> 2] + (size_t)(q0 + r) * HD + c);
            *reinterpret_cast<uint4*>(qdst[i >> 2] + r * APITCH + c) = v;
        }
    }
    __syncthreads();

    const int a_row = lane & 15;
    const int a_k   = (lane >> 4) << 3;
    uint32_t qfh[4][4], qfl[4][4];
#pragma unroll
    for (int ks = 0; ks < 4; ks++) {
        uint32_t off = (uint32_t)((wm + a_row) * APITCH + ks * 16 + a_k) * 2u;
        LDM_X4(qfh[ks][0], qfh[ks][1], qfh[ks][2], qfh[ks][3], Qh_u + off);
        LDM_X4(qfl[ks][0], qfl[ks][1], qfl[ks][2], qfl[ks][3], Ql_u + off);
    }

    const int b_n = (lane & 7) + ((lane >> 4) << 3);
    const int b_k = lane & 8;

    float m0 = -1e30f, m1 = -1e30f, l0 = 0.f, l1 = 0.f;
    float O[8][4];
#pragma unroll
    for (int d = 0; d < 8; d++)
#pragma unroll
        for (int r = 0; r < 4; r++) O[d][r] = 0.f;

    for (int t = 0; t < NT; t++) {
        if (t < NT - 1) { CP_WAIT1(); } else { CP_WAIT0(); }
        __syncthreads();

        const uint32_t Ks_h = buf_u[t & 1];
        const uint32_t Ks_l = Ks_h + KVARR_EL * 2u;
        const uint32_t Vs_h = Ks_h + 2u * KVARR_EL * 2u;
        const uint32_t Vs_l = Ks_h + 3u * KVARR_EL * 2u;

        float S[8][4];
#pragma unroll
        for (int nt = 0; nt < 8; nt++)
#pragma unroll
            for (int r = 0; r < 4; r++) S[nt][r] = 0.f;

#pragma unroll
        for (int ks = 0; ks < 4; ks++) {
            uint32_t kfh[4][4], kfl[4][4];
#pragma unroll
            for (int p = 0; p < 4; p++) {
                uint32_t off = (uint32_t)((p * 16 + b_n) * APITCH + ks * 16 + b_k) * 2u;
                LDM_X4(kfh[p][0], kfh[p][1], kfh[p][2], kfh[p][3], Ks_h + off);
                LDM_X4(kfl[p][0], kfl[p][1], kfl[p][2], kfl[p][3], Ks_l + off);
            }
#pragma unroll
            for (int nt = 0; nt < 8; nt++) {
                int p = nt >> 1;
                int o = (nt & 1) * 2;
                MMA_BF16(S[nt], qfh[ks], kfh[p][o], kfh[p][o+1]);
                MMA_BF16(S[nt], qfh[ks], kfl[p][o], kfl[p][o+1]);
                MMA_BF16(S[nt], qfl[ks], kfh[p][o], kfh[p][o+1]);
            }
        }

        float mx0 = -1e30f, mx1 = -1e30f;
#pragma unroll
        for (int nt = 0; nt < 8; nt++) {
            mx0 = fmaxf(mx0, fmaxf(S[nt][0], S[nt][1]));
            mx1 = fmaxf(mx1, fmaxf(S[nt][2], S[nt][3]));
        }
        mx0 = fmaxf(mx0, __shfl_xor_sync(0xffffffffu, mx0, 1));
        mx0 = fmaxf(mx0, __shfl_xor_sync(0xffffffffu, mx0, 2));
        mx1 = fmaxf(mx1, __shfl_xor_sync(0xffffffffu, mx1, 1));
        mx1 = fmaxf(mx1, __shfl_xor_sync(0xffffffffu, mx1, 2));
        float mn0 = fmaxf(m0, mx0), mn1 = fmaxf(m1, mx1);
        float c0 = __expf(m0 - mn0), c1 = __expf(m1 - mn1);
        m0 = mn0; m1 = mn1;

        float s0 = 0.f, s1 = 0.f;
#pragma unroll
        for (int nt = 0; nt < 8; nt++) {
            S[nt][0] = __expf(S[nt][0] - m0);
            S[nt][1] = __expf(S[nt][1] - m0);
            S[nt][2] = __expf(S[nt][2] - m1);
            S[nt][3] = __expf(S[nt][3] - m1);
            s0 += S[nt][0] + S[nt][1];
            s1 += S[nt][2] + S[nt][3];
        }
        s0 += __shfl_xor_sync(0xffffffffu, s0, 1);
        s0 += __shfl_xor_sync(0xffffffffu, s0, 2);
        s1 += __shfl_xor_sync(0xffffffffu, s1, 1);
        s1 += __shfl_xor_sync(0xffffffffu, s1, 2);
        l0 = l0 * c0 + s0;
        l1 = l1 * c1 + s1;
#pragma unroll
        for (int d = 0; d < 8; d++) {
            O[d][0] *= c0; O[d][1] *= c0;
            O[d][2] *= c1; O[d][3] *= c1;
        }

        uint32_t pfh[4][4], pfl[4][4];
#pragma unroll
        for (int ks = 0; ks < 4; ks++) {
            bf16_split2(S[2*ks][0],   S[2*ks][1],   pfh[ks][0], pfl[ks][0]);
            bf16_split2(S[2*ks][2],   S[2*ks][3],   pfh[ks][1], pfl[ks][1]);
            bf16_split2(S[2*ks+1][0], S[2*ks+1][1], pfh[ks][2], pfl[ks][2]);
            bf16_split2(S[2*ks+1][2], S[2*ks+1][3], pfh[ks][3], pfl[ks][3]);
        }

#pragma unroll
        for (int ks = 0; ks < 4; ks++) {
            uint32_t vfh[4][4], vfl[4][4];
#pragma unroll
            for (int pd = 0; pd < 4; pd++) {
                uint32_t off = (uint32_t)((ks * 16 + (lane & 15)) * APITCH +
                                          pd * 16 + ((lane >> 4) << 3)) * 2u;
                LDM_X4T(vfh[pd][0], vfh[pd][1], vfh[pd][2], vfh[pd][3], Vs_h + off);
                LDM_X4T(vfl[pd][0], vfl[pd][1], vfl[pd][2], vfl[pd][3], Vs_l + off);
            }
#pragma unroll
            for (int dt = 0; dt < 8; dt++) {
                int pd = dt >> 1;
                int o  = (dt & 1) * 2;
                MMA_BF16(O[dt], pfh[ks], vfh[pd][o], vfh[pd][o+1]);
                MMA_BF16(O[dt], pfh[ks], vfl[pd][o], vfl[pd][o+1]);
                MMA_BF16(O[dt], pfl[ks], vfh[pd][o], vfh[pd][o+1]);
            }
        }

        __syncthreads();
        if (t + 2 < NT) issue(t + 2, t & 1);
    }

    // epilogue: bf16 hi/lo of O/l -> [b*s][h*64+d]
    const int g  = lane >> 2;
    const int t2 = (lane & 3) * 2;
    const int b  = bh >> 4;
    const int h  = bh & 15;
    float inv0 = 1.0f / l0, inv1 = 1.0f / l1;
    int row = b * SS + q0 + wm + g;
#pragma unroll
    for (int dt = 0; dt < 8; dt++) {
        int col = h * HD + dt * 8 + t2;
        uint32_t hi, lo;
        bf16_split2(O[dt][0] * inv0, O[dt][1] * inv0, hi, lo);
        *reinterpret_cast<uint32_t*>(&aoh[(size_t)row * HID + col]) = hi;
        *reinterpret_cast<uint32_t*>(&aol[(size_t)row * HID + col]) = lo;
        bf16_split2(O[dt][2] * inv1, O[dt][3] * inv1, hi, lo);
        *reinterpret_cast<uint32_t*>(&aoh[(size_t)(row + 8) * HID + col]) = hi;
        *reinterpret_cast<uint32_t*>(&aol[(size_t)(row + 8) * HID + col]) = lo;
    }
}

// ----------------------------------------------------------------------------
// Launch
// ----------------------------------------------------------------------------
extern "C" void kernel_launch(void* const* d_in, const int* in_sizes, int n_in,
                              void* d_out, int out_size)
{
    const float* x     = (const float*)d_in[0];
    const float* q_w   = (const float*)d_in[1];
    const float* q_b   = (const float*)d_in[2];
    const float* kv_w  = (const float*)d_in[3];
    const float* kv_b  = (const float*)d_in[4];
    const float* gq    = (const float*)d_in[5];
    const float* gk    = (const float*)d_in[6];
    const float* out_w = (const float*)d_in[7];
    float* out = (float*)d_out;

    __nv_bfloat16 *pqh, *pql, *pkh, *pkl, *pvh, *pvl;
    cudaGetSymbolAddress((void**)&pqh, g_qh);
    cudaGetSymbolAddress((void**)&pql, g_ql);
    cudaGetSymbolAddress((void**)&pkh, g_kh);
    cudaGetSymbolAddress((void**)&pkl, g_kl);
    cudaGetSymbolAddress((void**)&pvh, g_vh);
    cudaGetSymbolAddress((void**)&pvl, g_vl);
    __nv_bfloat16 *pxh, *pxl, *paoh, *paol, *pwh, *pwl, *powh, *powl;
    cudaGetSymbolAddress((void**)&pxh,  g_xh);
    cudaGetSymbolAddress((void**)&pxl,  g_xl);
    cudaGetSymbolAddress((void**)&paoh, g_aoh);
    cudaGetSymbolAddress((void**)&paol, g_aol);
    cudaGetSymbolAddress((void**)&pwh,  g_wh);
    cudaGetSymbolAddress((void**)&pwl,  g_wl);
    cudaGetSymbolAddress((void**)&powh, g_owh);
    cudaGetSymbolAddress((void**)&powl, g_owl);

    cudaFuncSetAttribute(attn_mma,
                         cudaFuncAttributeMaxDynamicSharedMemorySize, ATT_SMEM);

    // Pre-split inputs and weights (q_w and kv_w into one concat buffer)
    {
        int n4 = MR * HID / 4;
        split_f32<<<(n4 + 255) / 256, 256>>>(x, pxh, pxl, n4);
        n4 = HID * HID / 4;
        split_f32<<<(n4 + 255) / 256, 256>>>(q_w, pwh, pwl, n4);
        n4 = 2 * HID * HID / 4;
        split_f32<<<(n4 + 255) / 256, 256>>>(kv_w, pwh + (size_t)HID * HID,
                                             pwl + (size_t)HID * HID, n4);
        n4 = HID * HID / 4;
        split_f32<<<(n4 + 255) / 256, 256>>>(out_w, powh, powl, n4);
    }
    // Merged QKV projection + fused qknorm/split/relayout
    {
        dim3 grid((3 * HID) / 128, MR / 128);   // (24, 64)
        gemm_qkv<<<grid, 256>>>(pxh, pxl, pwh, pwl, q_b, kv_b, gq, gk);
    }
    // Attention (tensor cores, 128 queries/CTA)
    {
        dim3 grid(SS / 128, BB * NH);           // (16, 64)
        attn_mma<<<grid, 256, ATT_SMEM>>>(pqh, pql, pkh, pkl, pvh, pvl, paoh, paol);
    }
    // Output projection
    {
        dim3 grid(HID / 128, MR / 128);
        gemm_pre<<<grid, 256>>>(paoh, paol, powh, powl, out, MR, HID, HID);
    }
}

// round 8
// speedup vs baseline: 1.0335x; 1.0081x over previous
#include <cuda_runtime.h>
#include <cuda_bf16.h>
#include <math.h>
#include <stdint.h>

// Problem constants
#define BB   4
#define SS   2048
#define HID  1024
#define NH   16
#define HD   64
#define MR   (BB*SS)   // 8192 rows

// Pre-split bf16 operands for attention, layout [b][h][s][64]
__device__ __nv_bfloat16 g_qh[(size_t)MR * HID];
__device__ __nv_bfloat16 g_ql[(size_t)MR * HID];
__device__ __nv_bfloat16 g_kh[(size_t)MR * HID];
__device__ __nv_bfloat16 g_kl[(size_t)MR * HID];
__device__ __nv_bfloat16 g_vh[(size_t)MR * HID];
__device__ __nv_bfloat16 g_vl[(size_t)MR * HID];
// Pre-split GEMM operands
__device__ __nv_bfloat16 g_xh [(size_t)MR * HID];
__device__ __nv_bfloat16 g_xl [(size_t)MR * HID];
__device__ __nv_bfloat16 g_aoh[(size_t)MR * HID];
__device__ __nv_bfloat16 g_aol[(size_t)MR * HID];
__device__ __nv_bfloat16 g_wh [(size_t)3 * HID * HID];   // concat(q_w, kv_w)
__device__ __nv_bfloat16 g_wl [(size_t)3 * HID * HID];
__device__ __nv_bfloat16 g_owh[(size_t)HID * HID];
__device__ __nv_bfloat16 g_owl[(size_t)HID * HID];

__device__ __forceinline__ uint32_t smem_u32(const void* p) {
    uint32_t a;
    asm("{ .reg .u64 t; cvta.to.shared.u64 t, %1; cvt.u32.u64 %0, t; }"
        : "=r"(a) : "l"(p));
    return a;
}

__device__ __forceinline__ void bf16_split2(float x, float y,
                                            uint32_t& hi, uint32_t& lo) {
    __nv_bfloat16 hx = __float2bfloat16(x);
    __nv_bfloat16 hy = __float2bfloat16(y);
    __nv_bfloat16 lx = __float2bfloat16(x - __bfloat162float(hx));
    __nv_bfloat16 ly = __float2bfloat16(y - __bfloat162float(hy));
    __nv_bfloat162 h; h.x = hx; h.y = hy;
    __nv_bfloat162 l; l.x = lx; l.y = ly;
    hi = *reinterpret_cast<uint32_t*>(&h);
    lo = *reinterpret_cast<uint32_t*>(&l);
}

#define LDM_X4(r0, r1, r2, r3, addr) \
    asm volatile("ldmatrix.sync.aligned.m8n8.x4.shared.b16 {%0,%1,%2,%3}, [%4];" \
                 : "=r"(r0), "=r"(r1), "=r"(r2), "=r"(r3) : "r"(addr))
#define LDM_X4T(r0, r1, r2, r3, addr) \
    asm volatile("ldmatrix.sync.aligned.m8n8.x4.trans.shared.b16 {%0,%1,%2,%3}, [%4];" \
                 : "=r"(r0), "=r"(r1), "=r"(r2), "=r"(r3) : "r"(addr))

#define MMA_BF16(d, a, b0v, b1v) \
    asm volatile("mma.sync.aligned.m16n8k16.row.col.f32.bf16.bf16.f32 " \
                 "{%0,%1,%2,%3}, {%4,%5,%6,%7}, {%8,%9}, {%0,%1,%2,%3};" \
                 : "+f"((d)[0]), "+f"((d)[1]), "+f"((d)[2]), "+f"((d)[3]) \
                 : "r"((a)[0]), "r"((a)[1]), "r"((a)[2]), "r"((a)[3]), \
                   "r"(b0v), "r"(b1v))

#define CP_ASYNC16(dst, src) \
    asm volatile("cp.async.cg.shared.global [%0], [%1], 16;" \
                 :: "r"(dst), "l"(src) : "memory")
#define CP_COMMIT() asm volatile("cp.async.commit_group;" ::: "memory")
#define CP_WAIT1()  asm volatile("cp.async.wait_group 1;" ::: "memory")
#define CP_WAIT0()  asm volatile("cp.async.wait_group 0;" ::: "memory")

// ============================================================================
// Merged split: fp32 -> bf16 hi/lo for x, q_w, kv_w, out_w in ONE launch
// ============================================================================
#define NX4   (MR * HID / 4)
#define NQW4  (HID * HID / 4)
#define NKVW4 (2 * HID * HID / 4)
#define NOW4  (HID * HID / 4)
#define NSPLIT4 (NX4 + NQW4 + NKVW4 + NOW4)

__global__ __launch_bounds__(256)
void split_all(const float* __restrict__ x, const float* __restrict__ qw,
               const float* __restrict__ kvw, const float* __restrict__ ow)
{
    int i = blockIdx.x * blockDim.x + threadIdx.x;
    if (i >= NSPLIT4) return;
    const float* src;
    __nv_bfloat16 *dh, *dl;
    int off;
    if (i < NX4) {
        src = x; dh = g_xh; dl = g_xl; off = i;
    } else if (i < NX4 + NQW4) {
        src = qw; dh = g_wh; dl = g_wl; off = i - NX4;
    } else if (i < NX4 + NQW4 + NKVW4) {
        src = kvw; off = i - NX4 - NQW4;
        dh = g_wh + (size_t)HID * HID; dl = g_wl + (size_t)HID * HID;
    } else {
        src = ow; dh = g_owh; dl = g_owl; off = i - NX4 - NQW4 - NKVW4;
    }
    float4 v = *reinterpret_cast<const float4*>(src + (size_t)off * 4);
    uint32_t h0, l0, h1, l1;
    bf16_split2(v.x, v.y, h0, l0);
    bf16_split2(v.z, v.w, h1, l1);
    *reinterpret_cast<uint2*>(dh + (size_t)off * 4) = make_uint2(h0, h1);
    *reinterpret_cast<uint2*>(dl + (size_t)off * 4) = make_uint2(l0, l1);
}

// ============================================================================
// Shared GEMM pieces
// ============================================================================
#define KC    32
#define PITCH 40
#define GT_EL (128 * PITCH)
#define GSTAGE_EL (4 * GT_EL)

// Term-major GEMM mainloop body (identical math; RAW distance 8 on accs).
// Processes mt pairs to stay under the 128-reg cap at 2 CTAs/SM.
#define GEMM_MAINLOOP(acc)                                                        \
    for (int s = 0; s < NS; s++) {                                                \
        if (s < NS - 1) { CP_WAIT1(); } else { CP_WAIT0(); }                      \
        __syncthreads();                                                          \
        const uint32_t bAh = sb_u + (uint32_t)((s & 1) * GSTAGE_EL) * 2u;         \
        const uint32_t bAl = bAh + (uint32_t)GT_EL * 2u;                          \
        const uint32_t bBh = bAh + (uint32_t)(2 * GT_EL) * 2u;                    \
        const uint32_t bBl = bAh + (uint32_t)(3 * GT_EL) * 2u;                    \
        _Pragma("unroll")                                                         \
        for (int kk = 0; kk < KC; kk += 16) {                                     \
            uint32_t bh[8], bl[8];                                                \
            _Pragma("unroll")                                                     \
            for (int p = 0; p < 2; p++) {                                         \
                uint32_t off = (uint32_t)((wn + p * 16 + b_n) * PITCH + kk + b_k) * 2u; \
                LDM_X4(bh[p*4+0], bh[p*4+1], bh[p*4+2], bh[p*4+3], bBh + off);    \
                LDM_X4(bl[p*4+0], bl[p*4+1], bl[p*4+2], bl[p*4+3], bBl + off);    \
            }                                                                     \
            _Pragma("unroll")                                                     \
            for (int mp = 0; mp < 2; mp++) {                                      \
                uint32_t ah[2][4], al[2][4];                                      \
                _Pragma("unroll")                                                 \
                for (int mi = 0; mi < 2; mi++) {                                  \
                    int mt = mp * 2 + mi;                                         \
                    uint32_t off = (uint32_t)((wm + mt * 16 + a_row) * PITCH + kk + a_k) * 2u; \
                    LDM_X4(ah[mi][0], ah[mi][1], ah[mi][2], ah[mi][3], bAh + off);\
                    LDM_X4(al[mi][0], al[mi][1], al[mi][2], al[mi][3], bAl + off);\
                }                                                                 \
                _Pragma("unroll")                                                 \
                for (int mi = 0; mi < 2; mi++)                                    \
                    _Pragma("unroll")                                             \
                    for (int nt = 0; nt < 4; nt++) {                              \
                        int p = nt >> 1, o = (nt & 1) * 2;                        \
                        MMA_BF16(acc[mp*2+mi][nt], ah[mi], bh[p*4+o], bh[p*4+o+1]); \
                    }                                                             \
                _Pragma("unroll")                                                 \
                for (int mi = 0; mi < 2; mi++)                                    \
                    _Pragma("unroll")                                             \
                    for (int nt = 0; nt < 4; nt++) {                              \
                        int p = nt >> 1, o = (nt & 1) * 2;                        \
                        MMA_BF16(acc[mp*2+mi][nt], ah[mi], bl[p*4+o], bl[p*4+o+1]); \
                    }                                                             \
                _Pragma("unroll")                                                 \
                for (int mi = 0; mi < 2; mi++)                                    \
                    _Pragma("unroll")                                             \
                    for (int nt = 0; nt < 4; nt++) {                              \
                        int p = nt >> 1, o = (nt & 1) * 2;                        \
                        MMA_BF16(acc[mp*2+mi][nt], al[mi], bh[p*4+o], bh[p*4+o+1]); \
                    }                                                             \
            }                                                                     \
        }                                                                         \
        __syncthreads();                                                          \
        if (s + 2 < NS) issue(s + 2, s & 1);                                      \
    }

// ============================================================================
// Merged QKV GEMM + fused qknorm/split/relayout epilogue.
// ============================================================================
__global__ __launch_bounds__(256, 2)
void gemm_qkv(const __nv_bfloat16* __restrict__ Ah, const __nv_bfloat16* __restrict__ Al,
              const __nv_bfloat16* __restrict__ Wh, const __nv_bfloat16* __restrict__ Wl,
              const float* __restrict__ q_b, const float* __restrict__ kv_b,
              const float* __restrict__ gq, const float* __restrict__ gk)
{
    __shared__ __align__(16) __nv_bfloat16 sbuf[2 * GSTAGE_EL];
    __shared__ float part[128][4];

    const int K = HID;
    const int tid  = threadIdx.x;
    const int wid  = tid >> 5;
    const int lane = tid & 31;
    const int row0 = blockIdx.y * 128;
    const int col0 = blockIdx.x * 128;
    const int wm   = (wid >> 2) * 64;
    const int wn   = (wid & 3) * 32;

    const uint32_t sb_u = smem_u32(sbuf);
    const __nv_bfloat16* srcs[4] = {
        Ah + (size_t)row0 * K, Al + (size_t)row0 * K,
        Wh + (size_t)col0 * K, Wl + (size_t)col0 * K };

    const int NS = K / KC;

    auto issue = [&](int s, int bsel) {
        const int k0 = s * KC;
        uint32_t base = sb_u + (uint32_t)bsel * GSTAGE_EL * 2u;
#pragma unroll
        for (int a = 0; a < 4; a++) {
#pragma unroll
            for (int t = 0; t < 2; t++) {
                int idx = tid + t * 256;
                int r   = idx >> 2;
                int c   = (idx & 3) * 8;
                uint32_t dst = base + (uint32_t)(a * GT_EL + r * PITCH + c) * 2u;
                CP_ASYNC16(dst, srcs[a] + (size_t)r * K + k0 + c);
            }
        }
        CP_COMMIT();
    };

    issue(0, 0);
    issue(1, 1);

    const int a_row = lane & 15;
    const int a_k   = (lane >> 4) << 3;
    const int b_n   = (lane & 7) + ((lane >> 4) << 3);
    const int b_k   = lane & 8;

    float acc[4][4][4];
#pragma unroll
    for (int mt = 0; mt < 4; mt++)
#pragma unroll
        for (int nt = 0; nt < 4; nt++)
#pragma unroll
            for (int r = 0; r < 4; r++) acc[mt][nt][r] = 0.f;

    GEMM_MAINLOOP(acc)

    // ---- fused epilogue ----
    const int g  = lane >> 2;
    const int t2 = (lane & 3) * 2;

#pragma unroll
    for (int nt = 0; nt < 4; nt++) {
        int col = col0 + wn + nt * 8 + t2;
        float b0 = (col < HID) ? __ldg(&q_b[col])     : __ldg(&kv_b[col - HID]);
        float b1 = (col + 1 < HID) ? __ldg(&q_b[col + 1]) : __ldg(&kv_b[col + 1 - HID]);
#pragma unroll
        for (int mt = 0; mt < 4; mt++) {
            acc[mt][nt][0] += b0; acc[mt][nt][1] += b1;
            acc[mt][nt][2] += b0; acc[mt][nt][3] += b1;
        }
    }

#pragma unroll
    for (int mt = 0; mt < 4; mt++) {
#pragma unroll
        for (int rh = 0; rh < 2; rh++) {
            float ssum = 0.f;
#pragma unroll
            for (int nt = 0; nt < 4; nt++) {
                float v0 = acc[mt][nt][rh * 2 + 0];
                float v1 = acc[mt][nt][rh * 2 + 1];
                ssum += v0 * v0 + v1 * v1;
            }
            ssum += __shfl_xor_sync(0xffffffffu, ssum, 1);
            ssum += __shfl_xor_sync(0xffffffffu, ssum, 2);
            if ((lane & 3) == 0)
                part[wm + mt * 16 + g + rh * 8][wn >> 5] = ssum;
        }
    }
    __syncthreads();

    const int seg = (col0 < HID) ? 0 : (col0 < 2 * HID) ? 1 : 2;
    const int h   = ((col0 & (HID - 1)) + wn) >> 6;
    const int hl2 = (wn >> 5) & ~1;
    __nv_bfloat16* dh = (seg == 0) ? g_qh : (seg == 1) ? g_kh : g_vh;
    __nv_bfloat16* dl = (seg == 0) ? g_ql : (seg == 1) ? g_kl : g_vl;
    const float* gamma = (seg == 0) ? gq : gk;

#pragma unroll
    for (int mt = 0; mt < 4; mt++) {
#pragma unroll
        for (int rh = 0; rh < 2; rh++) {
            int rloc = wm + mt * 16 + g + rh * 8;
            int row  = row0 + rloc;
            int b    = row >> 11;
            int srow = row & (SS - 1);
            float inv = 1.0f;
            if (seg < 2) {
                float hs = part[rloc][hl2] + part[rloc][hl2 + 1];
                inv = 8.0f / fmaxf(sqrtf(hs), 1e-12f);
            }
            size_t base = ((size_t)(b * NH + h) * SS + srow) * HD;
#pragma unroll
            for (int nt = 0; nt < 4; nt++) {
                int d = ((wn + nt * 8 + t2) & 63);
                float g0 = 1.f, g1 = 1.f;
                if (seg < 2) {
                    g0 = __ldg(&gamma[h * HD + d]);
                    g1 = __ldg(&gamma[h * HD + d + 1]);
                }
                float v0 = acc[mt][nt][rh * 2 + 0] * inv * g0;
                float v1 = acc[mt][nt][rh * 2 + 1] * inv * g1;
                uint32_t hi, lo;
                bf16_split2(v0, v1, hi, lo);
                *reinterpret_cast<uint32_t*>(&dh[base + d]) = hi;
                *reinterpret_cast<uint32_t*>(&dl[base + d]) = lo;
            }
        }
    }
}

// ============================================================================
// Out-proj GEMM (fp32 out), term-major mainloop.
// ============================================================================
__global__ __launch_bounds__(256, 2)
void gemm_pre(const __nv_bfloat16* __restrict__ Ah, const __nv_bfloat16* __restrict__ Al,
              const __nv_bfloat16* __restrict__ Wh, const __nv_bfloat16* __restrict__ Wl,
              float* __restrict__ C, int M, int N, int K)
{
    __shared__ __align__(16) __nv_bfloat16 sbuf[2 * GSTAGE_EL];

    const int tid  = threadIdx.x;
    const int wid  = tid >> 5;
    const int lane = tid & 31;
    const int row0 = blockIdx.y * 128;
    const int col0 = blockIdx.x * 128;
    const int wm   = (wid >> 2) * 64;
    const int wn   = (wid & 3) * 32;

    const uint32_t sb_u = smem_u32(sbuf);
    const __nv_bfloat16* srcs[4] = {
        Ah + (size_t)row0 * K, Al + (size_t)row0 * K,
        Wh + (size_t)col0 * K, Wl + (size_t)col0 * K };

    const int NS = K / KC;

    auto issue = [&](int s, int bsel) {
        const int k0 = s * KC;
        uint32_t base = sb_u + (uint32_t)bsel * GSTAGE_EL * 2u;
#pragma unroll
        for (int a = 0; a < 4; a++) {
#pragma unroll
            for (int t = 0; t < 2; t++) {
                int idx = tid + t * 256;
                int r   = idx >> 2;
                int c   = (idx & 3) * 8;
                uint32_t dst = base + (uint32_t)(a * GT_EL + r * PITCH + c) * 2u;
                CP_ASYNC16(dst, srcs[a] + (size_t)r * K + k0 + c);
            }
        }
        CP_COMMIT();
    };

    issue(0, 0);
    issue(1, 1);

    const int a_row = lane & 15;
    const int a_k   = (lane >> 4) << 3;
    const int b_n   = (lane & 7) + ((lane >> 4) << 3);
    const int b_k   = lane & 8;

    float acc[4][4][4];
#pragma unroll
    for (int mt = 0; mt < 4; mt++)
#pragma unroll
        for (int nt = 0; nt < 4; nt++)
#pragma unroll
            for (int r = 0; r < 4; r++) acc[mt][nt][r] = 0.f;

    GEMM_MAINLOOP(acc)

    const int g  = lane >> 2;
    const int t2 = (lane & 3) * 2;
#pragma unroll
    for (int mt = 0; mt < 4; mt++) {
#pragma unroll
        for (int nt = 0; nt < 4; nt++) {
            int row = row0 + wm + mt * 16 + g;
            int col = col0 + wn + nt * 8 + t2;
            *reinterpret_cast<float2*>(&C[(size_t)row * N + col]) =
                make_float2(acc[mt][nt][0], acc[mt][nt][1]);
            *reinterpret_cast<float2*>(&C[(size_t)(row + 8) * N + col]) =
                make_float2(acc[mt][nt][2], acc[mt][nt][3]);
        }
    }
}

// ============================================================================
// Tensor-core flash attention, term-major MMA passes, fused bf16 output.
// ============================================================================
#define APITCH 72
#define QTILE_EL  (128 * APITCH)
#define KVARR_EL  (64 * APITCH)
#define BUF_EL    (4 * KVARR_EL)
#define ATT_SMEM  ((2 * QTILE_EL + 2 * BUF_EL) * 2)
#define NT        (SS / 64)

__global__ __launch_bounds__(256, 1)
void attn_mma(const __nv_bfloat16* __restrict__ qh, const __nv_bfloat16* __restrict__ ql,
              const __nv_bfloat16* __restrict__ kh, const __nv_bfloat16* __restrict__ kl,
              const __nv_bfloat16* __restrict__ vh, const __nv_bfloat16* __restrict__ vl,
              __nv_bfloat16* __restrict__ aoh, __nv_bfloat16* __restrict__ aol)
{
    extern __shared__ __nv_bfloat16 sm[];
    __nv_bfloat16* Qh = sm;
    __nv_bfloat16* Ql = Qh + QTILE_EL;
    __nv_bfloat16* Bf = Ql + QTILE_EL;

    const int tid  = threadIdx.x;
    const int wid  = tid >> 5;
    const int lane = tid & 31;
    const int bh   = blockIdx.y;
    const int q0   = blockIdx.x * 128;
    const int wm   = wid * 16;
    const size_t bh_off = (size_t)bh * SS * HD;

    const __nv_bfloat16* srcs[4] = {kh + bh_off, kl + bh_off, vh + bh_off, vl + bh_off};
    const uint32_t buf_u[2] = { smem_u32(Bf), smem_u32(Bf + BUF_EL) };
    const uint32_t Qh_u = smem_u32(Qh);
    const uint32_t Ql_u = smem_u32(Ql);

    auto issue = [&](int kt, int bsel) {
#pragma unroll
        for (int i = 0; i < 8; i++) {
            const __nv_bfloat16* sp = srcs[i >> 1];
            int rem = ((i & 1) << 8) + tid;
            int r = rem >> 3;
            int c = (rem & 7) * 8;
            uint32_t dst = buf_u[bsel] + (uint32_t)((i >> 1) * KVARR_EL + r * APITCH + c) * 2u;
            CP_ASYNC16(dst, sp + (size_t)(kt * 64 + r) * HD + c);
        }
        CP_COMMIT();
    };

    issue(0, 0);
    issue(1, 1);

    {
        const __nv_bfloat16* qsrc[2] = {qh + bh_off, ql + bh_off};
        __nv_bfloat16* qdst[2] = {Qh, Ql};
#pragma unroll
        for (int i = 0; i < 8; i++) {
            int rem = ((i & 3) << 8) + tid;
            int r = rem >> 3;
            int c = (rem & 7) * 8;
            uint4 v = *reinterpret_cast<const uint4*>(
                qsrc[i >> 2] + (size_t)(q0 + r) * HD + c);
            *reinterpret_cast<uint4*>(qdst[i >> 2] + r * APITCH + c) = v;
        }
    }
    __syncthreads();

    const int a_row = lane & 15;
    const int a_k   = (lane >> 4) << 3;
    uint32_t qfh[4][4], qfl[4][4];
#pragma unroll
    for (int ks = 0; ks < 4; ks++) {
        uint32_t off = (uint32_t)((wm + a_row) * APITCH + ks * 16 + a_k) * 2u;
        LDM_X4(qfh[ks][0], qfh[ks][1], qfh[ks][2], qfh[ks][3], Qh_u + off);
        LDM_X4(qfl[ks][0], qfl[ks][1], qfl[ks][2], qfl[ks][3], Ql_u + off);
    }

    const int b_n = (lane & 7) + ((lane >> 4) << 3);
    const int b_k = lane & 8;

    float m0 = -1e30f, m1 = -1e30f, l0 = 0.f, l1 = 0.f;
    float O[8][4];
#pragma unroll
    for (int d = 0; d < 8; d++)
#pragma unroll
        for (int r = 0; r < 4; r++) O[d][r] = 0.f;

    for (int t = 0; t < NT; t++) {
        if (t < NT - 1) { CP_WAIT1(); } else { CP_WAIT0(); }
        __syncthreads();

        const uint32_t Ks_h = buf_u[t & 1];
        const uint32_t Ks_l = Ks_h + KVARR_EL * 2u;
        const uint32_t Vs_h = Ks_h + 2u * KVARR_EL * 2u;
        const uint32_t Vs_l = Ks_h + 3u * KVARR_EL * 2u;

        float S[8][4];
#pragma unroll
        for (int nt = 0; nt < 8; nt++)
#pragma unroll
            for (int r = 0; r < 4; r++) S[nt][r] = 0.f;

        // ---- S = Q K^T (term-major passes, RAW distance 8) ----
#pragma unroll
        for (int ks = 0; ks < 4; ks++) {
            uint32_t kfh[4][4], kfl[4][4];
#pragma unroll
            for (int p = 0; p < 4; p++) {
                uint32_t off = (uint32_t)((p * 16 + b_n) * APITCH + ks * 16 + b_k) * 2u;
                LDM_X4(kfh[p][0], kfh[p][1], kfh[p][2], kfh[p][3], Ks_h + off);
                LDM_X4(kfl[p][0], kfl[p][1], kfl[p][2], kfl[p][3], Ks_l + off);
            }
#pragma unroll
            for (int nt = 0; nt < 8; nt++) {
                int p = nt >> 1, o = (nt & 1) * 2;
                MMA_BF16(S[nt], qfh[ks], kfh[p][o], kfh[p][o+1]);
            }
#pragma unroll
            for (int nt = 0; nt < 8; nt++) {
                int p = nt >> 1, o = (nt & 1) * 2;
                MMA_BF16(S[nt], qfh[ks], kfl[p][o], kfl[p][o+1]);
            }
#pragma unroll
            for (int nt = 0; nt < 8; nt++) {
                int p = nt >> 1, o = (nt & 1) * 2;
                MMA_BF16(S[nt], qfl[ks], kfh[p][o], kfh[p][o+1]);
            }
        }

        float mx0 = -1e30f, mx1 = -1e30f;
#pragma unroll
        for (int nt = 0; nt < 8; nt++) {
            mx0 = fmaxf(mx0, fmaxf(S[nt][0], S[nt][1]));
            mx1 = fmaxf(mx1, fmaxf(S[nt][2], S[nt][3]));
        }
        mx0 = fmaxf(mx0, __shfl_xor_sync(0xffffffffu, mx0, 1));
        mx0 = fmaxf(mx0, __shfl_xor_sync(0xffffffffu, mx0, 2));
        mx1 = fmaxf(mx1, __shfl_xor_sync(0xffffffffu, mx1, 1));
        mx1 = fmaxf(mx1, __shfl_xor_sync(0xffffffffu, mx1, 2));
        float mn0 = fmaxf(m0, mx0), mn1 = fmaxf(m1, mx1);
        float c0 = __expf(m0 - mn0), c1 = __expf(m1 - mn1);
        m0 = mn0; m1 = mn1;

        float s0 = 0.f, s1 = 0.f;
#pragma unroll
        for (int nt = 0; nt < 8; nt++) {
            S[nt][0] = __expf(S[nt][0] - m0);
            S[nt][1] = __expf(S[nt][1] - m0);
            S[nt][2] = __expf(S[nt][2] - m1);
            S[nt][3] = __expf(S[nt][3] - m1);
            s0 += S[nt][0] + S[nt][1];
            s1 += S[nt][2] + S[nt][3];
        }
        s0 += __shfl_xor_sync(0xffffffffu, s0, 1);
        s0 += __shfl_xor_sync(0xffffffffu, s0, 2);
        s1 += __shfl_xor_sync(0xffffffffu, s1, 1);
        s1 += __shfl_xor_sync(0xffffffffu, s1, 2);
        l0 = l0 * c0 + s0;
        l1 = l1 * c1 + s1;
#pragma unroll
        for (int d = 0; d < 8; d++) {
            O[d][0] *= c0; O[d][1] *= c0;
            O[d][2] *= c1; O[d][3] *= c1;
        }

        uint32_t pfh[4][4], pfl[4][4];
#pragma unroll
        for (int ks = 0; ks < 4; ks++) {
            bf16_split2(S[2*ks][0],   S[2*ks][1],   pfh[ks][0], pfl[ks][0]);
            bf16_split2(S[2*ks][2],   S[2*ks][3],   pfh[ks][1], pfl[ks][1]);
            bf16_split2(S[2*ks+1][0], S[2*ks+1][1], pfh[ks][2], pfl[ks][2]);
            bf16_split2(S[2*ks+1][2], S[2*ks+1][3], pfh[ks][3], pfl[ks][3]);
        }

        // ---- O += P V (term-major passes) ----
#pragma unroll
        for (int ks = 0; ks < 4; ks++) {
            uint32_t vfh[4][4], vfl[4][4];
#pragma unroll
            for (int pd = 0; pd < 4; pd++) {
                uint32_t off = (uint32_t)((ks * 16 + (lane & 15)) * APITCH +
                                          pd * 16 + ((lane >> 4) << 3)) * 2u;
                LDM_X4T(vfh[pd][0], vfh[pd][1], vfh[pd][2], vfh[pd][3], Vs_h + off);
                LDM_X4T(vfl[pd][0], vfl[pd][1], vfl[pd][2], vfl[pd][3], Vs_l + off);
            }
#pragma unroll
            for (int dt = 0; dt < 8; dt++) {
                int pd = dt >> 1, o = (dt & 1) * 2;
                MMA_BF16(O[dt], pfh[ks], vfh[pd][o], vfh[pd][o+1]);
            }
#pragma unroll
            for (int dt = 0; dt < 8; dt++) {
                int pd = dt >> 1, o = (dt & 1) * 2;
                MMA_BF16(O[dt], pfh[ks], vfl[pd][o], vfl[pd][o+1]);
            }
#pragma unroll
            for (int dt = 0; dt < 8; dt++) {
                int pd = dt >> 1, o = (dt & 1) * 2;
                MMA_BF16(O[dt], pfl[ks], vfh[pd][o], vfh[pd][o+1]);
            }
        }

        __syncthreads();
        if (t + 2 < NT) issue(t + 2, t & 1);
    }

    const int g  = lane >> 2;
    const int t2 = (lane & 3) * 2;
    const int b  = bh >> 4;
    const int h  = bh & 15;
    float inv0 = 1.0f / l0, inv1 = 1.0f / l1;
    int row = b * SS + q0 + wm + g;
#pragma unroll
    for (int dt = 0; dt < 8; dt++) {
        int col = h * HD + dt * 8 + t2;
        uint32_t hi, lo;
        bf16_split2(O[dt][0] * inv0, O[dt][1] * inv0, hi, lo);
        *reinterpret_cast<uint32_t*>(&aoh[(size_t)row * HID + col]) = hi;
        *reinterpret_cast<uint32_t*>(&aol[(size_t)row * HID + col]) = lo;
        bf16_split2(O[dt][2] * inv1, O[dt][3] * inv1, hi, lo);
        *reinterpret_cast<uint32_t*>(&aoh[(size_t)(row + 8) * HID + col]) = hi;
        *reinterpret_cast<uint32_t*>(&aol[(size_t)(row + 8) * HID + col]) = lo;
    }
}

// ----------------------------------------------------------------------------
// Launch
// ----------------------------------------------------------------------------
extern "C" void kernel_launch(void* const* d_in, const int* in_sizes, int n_in,
                              void* d_out, int out_size)
{
    const float* x     = (const float*)d_in[0];
    const float* q_w   = (const float*)d_in[1];
    const float* q_b   = (const float*)d_in[2];
    const float* kv_w  = (const float*)d_in[3];
    const float* kv_b  = (const float*)d_in[4];
    const float* gq    = (const float*)d_in[5];
    const float* gk    = (const float*)d_in[6];
    const float* out_w = (const float*)d_in[7];
    float* out = (float*)d_out;

    __nv_bfloat16 *pqh, *pql, *pkh, *pkl, *pvh, *pvl;
    cudaGetSymbolAddress((void**)&pqh, g_qh);
    cudaGetSymbolAddress((void**)&pql, g_ql);
    cudaGetSymbolAddress((void**)&pkh, g_kh);
    cudaGetSymbolAddress((void**)&pkl, g_kl);
    cudaGetSymbolAddress((void**)&pvh, g_vh);
    cudaGetSymbolAddress((void**)&pvl, g_vl);
    __nv_bfloat16 *pxh, *pxl, *paoh, *paol, *pwh, *pwl, *powh, *powl;
    cudaGetSymbolAddress((void**)&pxh,  g_xh);
    cudaGetSymbolAddress((void**)&pxl,  g_xl);
    cudaGetSymbolAddress((void**)&paoh, g_aoh);
    cudaGetSymbolAddress((void**)&paol, g_aol);
    cudaGetSymbolAddress((void**)&pwh,  g_wh);
    cudaGetSymbolAddress((void**)&pwl,  g_wl);
    cudaGetSymbolAddress((void**)&powh, g_owh);
    cudaGetSymbolAddress((void**)&powl, g_owl);

    cudaFuncSetAttribute(attn_mma,
                         cudaFuncAttributeMaxDynamicSharedMemorySize, ATT_SMEM);

    // Pre-split inputs + all weights (one launch)
    split_all<<<(NSPLIT4 + 255) / 256, 256>>>(x, q_w, kv_w, out_w);

    // Merged QKV projection + fused qknorm/split/relayout
    {
        dim3 grid((3 * HID) / 128, MR / 128);   // (24, 64)
        gemm_qkv<<<grid, 256>>>(pxh, pxl, pwh, pwl, q_b, kv_b, gq, gk);
    }
    // Attention (tensor cores, 128 queries/CTA)
    {
        dim3 grid(SS / 128, BB * NH);           // (16, 64)
        attn_mma<<<grid, 256, ATT_SMEM>>>(pqh, pql, pkh, pkl, pvh, pvl, paoh, paol);
    }
    // Output projection
    {
        dim3 grid(HID / 128, MR / 128);
        gemm_pre<<<grid, 256>>>(paoh, paol, powh, powl, out, MR, HID, HID);
    }
}

// round 9
// speedup vs baseline: 1.1106x; 1.0746x over previous
#include <cuda_runtime.h>
#include <cuda_bf16.h>
#include <math.h>
#include <stdint.h>

// Problem constants
#define BB   4
#define SS   2048
#define HID  1024
#define NH   16
#define HD   64
#define MR   (BB*SS)   // 8192 rows

// Pre-split bf16 operands for attention, layout [b][h][s][64]
__device__ __nv_bfloat16 g_qh[(size_t)MR * HID];
__device__ __nv_bfloat16 g_ql[(size_t)MR * HID];
__device__ __nv_bfloat16 g_kh[(size_t)MR * HID];
__device__ __nv_bfloat16 g_kl[(size_t)MR * HID];
__device__ __nv_bfloat16 g_vh[(size_t)MR * HID];
__device__ __nv_bfloat16 g_vl[(size_t)MR * HID];
// Pre-split GEMM operands
__device__ __nv_bfloat16 g_xh [(size_t)MR * HID];
__device__ __nv_bfloat16 g_xl [(size_t)MR * HID];
__device__ __nv_bfloat16 g_aoh[(size_t)MR * HID];
__device__ __nv_bfloat16 g_aol[(size_t)MR * HID];
__device__ __nv_bfloat16 g_wh [(size_t)3 * HID * HID];   // concat(q_w, kv_w)
__device__ __nv_bfloat16 g_wl [(size_t)3 * HID * HID];
__device__ __nv_bfloat16 g_owh[(size_t)HID * HID];
__device__ __nv_bfloat16 g_owl[(size_t)HID * HID];

__device__ __forceinline__ uint32_t smem_u32(const void* p) {
    uint32_t a;
    asm("{ .reg .u64 t; cvta.to.shared.u64 t, %1; cvt.u32.u64 %0, t; }"
        : "=r"(a) : "l"(p));
    return a;
}

__device__ __forceinline__ void bf16_split2(float x, float y,
                                            uint32_t& hi, uint32_t& lo) {
    __nv_bfloat16 hx = __float2bfloat16(x);
    __nv_bfloat16 hy = __float2bfloat16(y);
    __nv_bfloat16 lx = __float2bfloat16(x - __bfloat162float(hx));
    __nv_bfloat16 ly = __float2bfloat16(y - __bfloat162float(hy));
    __nv_bfloat162 h; h.x = hx; h.y = hy;
    __nv_bfloat162 l; l.x = lx; l.y = ly;
    hi = *reinterpret_cast<uint32_t*>(&h);
    lo = *reinterpret_cast<uint32_t*>(&l);
}

#define LDM_X4(r0, r1, r2, r3, addr) \
    asm volatile("ldmatrix.sync.aligned.m8n8.x4.shared.b16 {%0,%1,%2,%3}, [%4];" \
                 : "=r"(r0), "=r"(r1), "=r"(r2), "=r"(r3) : "r"(addr))
#define LDM_X4T(r0, r1, r2, r3, addr) \
    asm volatile("ldmatrix.sync.aligned.m8n8.x4.trans.shared.b16 {%0,%1,%2,%3}, [%4];" \
                 : "=r"(r0), "=r"(r1), "=r"(r2), "=r"(r3) : "r"(addr))

#define MMA_BF16(d, a, b0v, b1v) \
    asm volatile("mma.sync.aligned.m16n8k16.row.col.f32.bf16.bf16.f32 " \
                 "{%0,%1,%2,%3}, {%4,%5,%6,%7}, {%8,%9}, {%0,%1,%2,%3};" \
                 : "+f"((d)[0]), "+f"((d)[1]), "+f"((d)[2]), "+f"((d)[3]) \
                 : "r"((a)[0]), "r"((a)[1]), "r"((a)[2]), "r"((a)[3]), \
                   "r"(b0v), "r"(b1v))

#define CP_ASYNC16(dst, src) \
    asm volatile("cp.async.cg.shared.global [%0], [%1], 16;" \
                 :: "r"(dst), "l"(src) : "memory")
#define CP_COMMIT() asm volatile("cp.async.commit_group;" ::: "memory")
#define CP_WAIT1()  asm volatile("cp.async.wait_group 1;" ::: "memory")
#define CP_WAIT0()  asm volatile("cp.async.wait_group 0;" ::: "memory")

// ============================================================================
// Merged split: fp32 -> bf16 hi/lo for x, q_w, kv_w, out_w in ONE launch
// ============================================================================
#define NX4   (MR * HID / 4)
#define NQW4  (HID * HID / 4)
#define NKVW4 (2 * HID * HID / 4)
#define NOW4  (HID * HID / 4)
#define NSPLIT4 (NX4 + NQW4 + NKVW4 + NOW4)

__global__ __launch_bounds__(256)
void split_all(const float* __restrict__ x, const float* __restrict__ qw,
               const float* __restrict__ kvw, const float* __restrict__ ow)
{
    int i = blockIdx.x * blockDim.x + threadIdx.x;
    if (i >= NSPLIT4) return;
    const float* src;
    __nv_bfloat16 *dh, *dl;
    int off;
    if (i < NX4) {
        src = x; dh = g_xh; dl = g_xl; off = i;
    } else if (i < NX4 + NQW4) {
        src = qw; dh = g_wh; dl = g_wl; off = i - NX4;
    } else if (i < NX4 + NQW4 + NKVW4) {
        src = kvw; off = i - NX4 - NQW4;
        dh = g_wh + (size_t)HID * HID; dl = g_wl + (size_t)HID * HID;
    } else {
        src = ow; dh = g_owh; dl = g_owl; off = i - NX4 - NQW4 - NKVW4;
    }
    float4 v = *reinterpret_cast<const float4*>(src + (size_t)off * 4);
    uint32_t h0, l0, h1, l1;
    bf16_split2(v.x, v.y, h0, l0);
    bf16_split2(v.z, v.w, h1, l1);
    *reinterpret_cast<uint2*>(dh + (size_t)off * 4) = make_uint2(h0, h1);
    *reinterpret_cast<uint2*>(dl + (size_t)off * 4) = make_uint2(l0, l1);
}

// ============================================================================
// Shared GEMM pieces (unchanged, round-8 proven)
// ============================================================================
#define KC    32
#define PITCH 40
#define GT_EL (128 * PITCH)
#define GSTAGE_EL (4 * GT_EL)

#define GEMM_MAINLOOP(acc)                                                        \
    for (int s = 0; s < NS; s++) {                                                \
        if (s < NS - 1) { CP_WAIT1(); } else { CP_WAIT0(); }                      \
        __syncthreads();                                                          \
        const uint32_t bAh = sb_u + (uint32_t)((s & 1) * GSTAGE_EL) * 2u;         \
        const uint32_t bAl = bAh + (uint32_t)GT_EL * 2u;                          \
        const uint32_t bBh = bAh + (uint32_t)(2 * GT_EL) * 2u;                    \
        const uint32_t bBl = bAh + (uint32_t)(3 * GT_EL) * 2u;                    \
        _Pragma("unroll")                                                         \
        for (int kk = 0; kk < KC; kk += 16) {                                     \
            uint32_t bh[8], bl[8];                                                \
            _Pragma("unroll")                                                     \
            for (int p = 0; p < 2; p++) {                                         \
                uint32_t off = (uint32_t)((wn + p * 16 + b_n) * PITCH + kk + b_k) * 2u; \
                LDM_X4(bh[p*4+0], bh[p*4+1], bh[p*4+2], bh[p*4+3], bBh + off);    \
                LDM_X4(bl[p*4+0], bl[p*4+1], bl[p*4+2], bl[p*4+3], bBl + off);    \
            }                                                                     \
            _Pragma("unroll")                                                     \
            for (int mp = 0; mp < 2; mp++) {                                      \
                uint32_t ah[2][4], al[2][4];                                      \
                _Pragma("unroll")                                                 \
                for (int mi = 0; mi < 2; mi++) {                                  \
                    int mt = mp * 2 + mi;                                         \
                    uint32_t off = (uint32_t)((wm + mt * 16 + a_row) * PITCH + kk + a_k) * 2u; \
                    LDM_X4(ah[mi][0], ah[mi][1], ah[mi][2], ah[mi][3], bAh + off);\
                    LDM_X4(al[mi][0], al[mi][1], al[mi][2], al[mi][3], bAl + off);\
                }                                                                 \
                _Pragma("unroll")                                                 \
                for (int mi = 0; mi < 2; mi++)                                    \
                    _Pragma("unroll")                                             \
                    for (int nt = 0; nt < 4; nt++) {                              \
                        int p = nt >> 1, o = (nt & 1) * 2;                        \
                        MMA_BF16(acc[mp*2+mi][nt], ah[mi], bh[p*4+o], bh[p*4+o+1]); \
                    }                                                             \
                _Pragma("unroll")                                                 \
                for (int mi = 0; mi < 2; mi++)                                    \
                    _Pragma("unroll")                                             \
                    for (int nt = 0; nt < 4; nt++) {                              \
                        int p = nt >> 1, o = (nt & 1) * 2;                        \
                        MMA_BF16(acc[mp*2+mi][nt], ah[mi], bl[p*4+o], bl[p*4+o+1]); \
                    }                                                             \
                _Pragma("unroll")                                                 \
                for (int mi = 0; mi < 2; mi++)                                    \
                    _Pragma("unroll")                                             \
                    for (int nt = 0; nt < 4; nt++) {                              \
                        int p = nt >> 1, o = (nt & 1) * 2;                        \
                        MMA_BF16(acc[mp*2+mi][nt], al[mi], bh[p*4+o], bh[p*4+o+1]); \
                    }                                                             \
            }                                                                     \
        }                                                                         \
        __syncthreads();                                                          \
        if (s + 2 < NS) issue(s + 2, s & 1);                                      \
    }

// ============================================================================
// Merged QKV GEMM + fused qknorm/split/relayout epilogue (round-8 proven).
// ============================================================================
__global__ __launch_bounds__(256, 2)
void gemm_qkv(const __nv_bfloat16* __restrict__ Ah, const __nv_bfloat16* __restrict__ Al,
              const __nv_bfloat16* __restrict__ Wh, const __nv_bfloat16* __restrict__ Wl,
              const float* __restrict__ q_b, const float* __restrict__ kv_b,
              const float* __restrict__ gq, const float* __restrict__ gk)
{
    __shared__ __align__(16) __nv_bfloat16 sbuf[2 * GSTAGE_EL];
    __shared__ float part[128][4];

    const int K = HID;
    const int tid  = threadIdx.x;
    const int wid  = tid >> 5;
    const int lane = tid & 31;
    const int row0 = blockIdx.y * 128;
    const int col0 = blockIdx.x * 128;
    const int wm   = (wid >> 2) * 64;
    const int wn   = (wid & 3) * 32;

    const uint32_t sb_u = smem_u32(sbuf);
    const __nv_bfloat16* srcs[4] = {
        Ah + (size_t)row0 * K, Al + (size_t)row0 * K,
        Wh + (size_t)col0 * K, Wl + (size_t)col0 * K };

    const int NS = K / KC;

    auto issue = [&](int s, int bsel) {
        const int k0 = s * KC;
        uint32_t base = sb_u + (uint32_t)bsel * GSTAGE_EL * 2u;
#pragma unroll
        for (int a = 0; a < 4; a++) {
#pragma unroll
            for (int t = 0; t < 2; t++) {
                int idx = tid + t * 256;
                int r   = idx >> 2;
                int c   = (idx & 3) * 8;
                uint32_t dst = base + (uint32_t)(a * GT_EL + r * PITCH + c) * 2u;
                CP_ASYNC16(dst, srcs[a] + (size_t)r * K + k0 + c);
            }
        }
        CP_COMMIT();
    };

    issue(0, 0);
    issue(1, 1);

    const int a_row = lane & 15;
    const int a_k   = (lane >> 4) << 3;
    const int b_n   = (lane & 7) + ((lane >> 4) << 3);
    const int b_k   = lane & 8;

    float acc[4][4][4];
#pragma unroll
    for (int mt = 0; mt < 4; mt++)
#pragma unroll
        for (int nt = 0; nt < 4; nt++)
#pragma unroll
            for (int r = 0; r < 4; r++) acc[mt][nt][r] = 0.f;

    GEMM_MAINLOOP(acc)

    const int g  = lane >> 2;
    const int t2 = (lane & 3) * 2;

#pragma unroll
    for (int nt = 0; nt < 4; nt++) {
        int col = col0 + wn + nt * 8 + t2;
        float b0 = (col < HID) ? __ldg(&q_b[col])     : __ldg(&kv_b[col - HID]);
        float b1 = (col + 1 < HID) ? __ldg(&q_b[col + 1]) : __ldg(&kv_b[col + 1 - HID]);
#pragma unroll
        for (int mt = 0; mt < 4; mt++) {
            acc[mt][nt][0] += b0; acc[mt][nt][1] += b1;
            acc[mt][nt][2] += b0; acc[mt][nt][3] += b1;
        }
    }

#pragma unroll
    for (int mt = 0; mt < 4; mt++) {
#pragma unroll
        for (int rh = 0; rh < 2; rh++) {
            float ssum = 0.f;
#pragma unroll
            for (int nt = 0; nt < 4; nt++) {
                float v0 = acc[mt][nt][rh * 2 + 0];
                float v1 = acc[mt][nt][rh * 2 + 1];
                ssum += v0 * v0 + v1 * v1;
            }
            ssum += __shfl_xor_sync(0xffffffffu, ssum, 1);
            ssum += __shfl_xor_sync(0xffffffffu, ssum, 2);
            if ((lane & 3) == 0)
                part[wm + mt * 16 + g + rh * 8][wn >> 5] = ssum;
        }
    }
    __syncthreads();

    const int seg = (col0 < HID) ? 0 : (col0 < 2 * HID) ? 1 : 2;
    const int h   = ((col0 & (HID - 1)) + wn) >> 6;
    const int hl2 = (wn >> 5) & ~1;
    __nv_bfloat16* dh = (seg == 0) ? g_qh : (seg == 1) ? g_kh : g_vh;
    __nv_bfloat16* dl = (seg == 0) ? g_ql : (seg == 1) ? g_kl : g_vl;
    const float* gamma = (seg == 0) ? gq : gk;

#pragma unroll
    for (int mt = 0; mt < 4; mt++) {
#pragma unroll
        for (int rh = 0; rh < 2; rh++) {
            int rloc = wm + mt * 16 + g + rh * 8;
            int row  = row0 + rloc;
            int b    = row >> 11;
            int srow = row & (SS - 1);
            float inv = 1.0f;
            if (seg < 2) {
                float hs = part[rloc][hl2] + part[rloc][hl2 + 1];
                inv = 8.0f / fmaxf(sqrtf(hs), 1e-12f);
            }
            size_t base = ((size_t)(b * NH + h) * SS + srow) * HD;
#pragma unroll
            for (int nt = 0; nt < 4; nt++) {
                int d = ((wn + nt * 8 + t2) & 63);
                float g0 = 1.f, g1 = 1.f;
                if (seg < 2) {
                    g0 = __ldg(&gamma[h * HD + d]);
                    g1 = __ldg(&gamma[h * HD + d + 1]);
                }
                float v0 = acc[mt][nt][rh * 2 + 0] * inv * g0;
                float v1 = acc[mt][nt][rh * 2 + 1] * inv * g1;
                uint32_t hi, lo;
                bf16_split2(v0, v1, hi, lo);
                *reinterpret_cast<uint32_t*>(&dh[base + d]) = hi;
                *reinterpret_cast<uint32_t*>(&dl[base + d]) = lo;
            }
        }
    }
}

// ============================================================================
// Out-proj GEMM (fp32 out) (round-8 proven).
// ============================================================================
__global__ __launch_bounds__(256, 2)
void gemm_pre(const __nv_bfloat16* __restrict__ Ah, const __nv_bfloat16* __restrict__ Al,
              const __nv_bfloat16* __restrict__ Wh, const __nv_bfloat16* __restrict__ Wl,
              float* __restrict__ C, int M, int N, int K)
{
    __shared__ __align__(16) __nv_bfloat16 sbuf[2 * GSTAGE_EL];

    const int tid  = threadIdx.x;
    const int wid  = tid >> 5;
    const int lane = tid & 31;
    const int row0 = blockIdx.y * 128;
    const int col0 = blockIdx.x * 128;
    const int wm   = (wid >> 2) * 64;
    const int wn   = (wid & 3) * 32;

    const uint32_t sb_u = smem_u32(sbuf);
    const __nv_bfloat16* srcs[4] = {
        Ah + (size_t)row0 * K, Al + (size_t)row0 * K,
        Wh + (size_t)col0 * K, Wl + (size_t)col0 * K };

    const int NS = K / KC;

    auto issue = [&](int s, int bsel) {
        const int k0 = s * KC;
        uint32_t base = sb_u + (uint32_t)bsel * GSTAGE_EL * 2u;
#pragma unroll
        for (int a = 0; a < 4; a++) {
#pragma unroll
            for (int t = 0; t < 2; t++) {
                int idx = tid + t * 256;
                int r   = idx >> 2;
                int c   = (idx & 3) * 8;
                uint32_t dst = base + (uint32_t)(a * GT_EL + r * PITCH + c) * 2u;
                CP_ASYNC16(dst, srcs[a] + (size_t)r * K + k0 + c);
            }
        }
        CP_COMMIT();
    };

    issue(0, 0);
    issue(1, 1);

    const int a_row = lane & 15;
    const int a_k   = (lane >> 4) << 3;
    const int b_n   = (lane & 7) + ((lane >> 4) << 3);
    const int b_k   = lane & 8;

    float acc[4][4][4];
#pragma unroll
    for (int mt = 0; mt < 4; mt++)
#pragma unroll
        for (int nt = 0; nt < 4; nt++)
#pragma unroll
            for (int r = 0; r < 4; r++) acc[mt][nt][r] = 0.f;

    GEMM_MAINLOOP(acc)

    const int g  = lane >> 2;
    const int t2 = (lane & 3) * 2;
#pragma unroll
    for (int mt = 0; mt < 4; mt++) {
#pragma unroll
        for (int nt = 0; nt < 4; nt++) {
            int row = row0 + wm + mt * 16 + g;
            int col = col0 + wn + nt * 8 + t2;
            *reinterpret_cast<float2*>(&C[(size_t)row * N + col]) =
                make_float2(acc[mt][nt][0], acc[mt][nt][1]);
            *reinterpret_cast<float2*>(&C[(size_t)(row + 8) * N + col]) =
                make_float2(acc[mt][nt][2], acc[mt][nt][3]);
        }
    }
}

// ============================================================================
// Tensor-core flash attention: 4 warps x 32 query rows (2 m-tiles/warp).
// K/V fragments loaded once per warp feed both m-tiles -> 1.6x less LDS
// traffic per query. Q reloaded from smem per tile (not hoisted).
// 128 threads, 2 CTAs/SM. Fused bf16 hi/lo output epilogue.
// ============================================================================
#define APITCH 72
#define QTILE_EL  (128 * APITCH)
#define KVARR_EL  (64 * APITCH)
#define BUF_EL    (4 * KVARR_EL)
#define ATT_SMEM  ((2 * QTILE_EL + 2 * BUF_EL) * 2)   // 110592 bytes
#define NT        (SS / 64)

__global__ __launch_bounds__(128, 2)
void attn_mma(const __nv_bfloat16* __restrict__ qh, const __nv_bfloat16* __restrict__ ql,
              const __nv_bfloat16* __restrict__ kh, const __nv_bfloat16* __restrict__ kl,
              const __nv_bfloat16* __restrict__ vh, const __nv_bfloat16* __restrict__ vl,
              __nv_bfloat16* __restrict__ aoh, __nv_bfloat16* __restrict__ aol)
{
    extern __shared__ __nv_bfloat16 sm[];
    __nv_bfloat16* Qh = sm;
    __nv_bfloat16* Ql = Qh + QTILE_EL;
    __nv_bfloat16* Bf = Ql + QTILE_EL;

    const int tid  = threadIdx.x;
    const int wid  = tid >> 5;
    const int lane = tid & 31;
    const int bh   = blockIdx.y;
    const int q0   = blockIdx.x * 128;
    const int wm   = wid * 32;              // 32 query rows per warp
    const size_t bh_off = (size_t)bh * SS * HD;

    const __nv_bfloat16* srcs[4] = {kh + bh_off, kl + bh_off, vh + bh_off, vl + bh_off};
    const uint32_t buf_u[2] = { smem_u32(Bf), smem_u32(Bf + BUF_EL) };
    const uint32_t Qh_u = smem_u32(Qh);
    const uint32_t Ql_u = smem_u32(Ql);

    // issue one 64-key KV stage: 4 arrays x 64 rows x 64 cols, 16B chunks, 128 thr
    auto issue = [&](int kt, int bsel) {
#pragma unroll
        for (int i = 0; i < 16; i++) {
            const __nv_bfloat16* sp = srcs[i >> 2];
            int rem = ((i & 3) << 7) + tid;
            int r = rem >> 3;
            int c = (rem & 7) * 8;
            uint32_t dst = buf_u[bsel] + (uint32_t)((i >> 2) * KVARR_EL + r * APITCH + c) * 2u;
            CP_ASYNC16(dst, sp + (size_t)(kt * 64 + r) * HD + c);
        }
        CP_COMMIT();
    };

    issue(0, 0);
    issue(1, 1);

    // Q tile: 128 rows hi/lo, 16B chunks, 128 threads
    {
        const __nv_bfloat16* qsrc[2] = {qh + bh_off, ql + bh_off};
        __nv_bfloat16* qdst[2] = {Qh, Ql};
#pragma unroll
        for (int i = 0; i < 16; i++) {
            int rem = ((i & 7) << 7) + tid;
            int r = rem >> 3;
            int c = (rem & 7) * 8;
            uint4 v = *reinterpret_cast<const uint4*>(
                qsrc[i >> 3] + (size_t)(q0 + r) * HD + c);
            *reinterpret_cast<uint4*>(qdst[i >> 3] + r * APITCH + c) = v;
        }
    }
    __syncthreads();

    const int a_row = lane & 15;
    const int a_k   = (lane >> 4) << 3;
    const int b_n   = (lane & 7) + ((lane >> 4) << 3);
    const int b_k   = lane & 8;

    float m_run[2][2], l_run[2][2];
    float O[2][8][4];
#pragma unroll
    for (int mt = 0; mt < 2; mt++) {
        m_run[mt][0] = -1e30f; m_run[mt][1] = -1e30f;
        l_run[mt][0] = 0.f;    l_run[mt][1] = 0.f;
#pragma unroll
        for (int d = 0; d < 8; d++)
#pragma unroll
            for (int r = 0; r < 4; r++) O[mt][d][r] = 0.f;
    }

    for (int t = 0; t < NT; t++) {
        if (t < NT - 1) { CP_WAIT1(); } else { CP_WAIT0(); }
        __syncthreads();

        const uint32_t Ks_h = buf_u[t & 1];
        const uint32_t Ks_l = Ks_h + KVARR_EL * 2u;
        const uint32_t Vs_h = Ks_h + 2u * KVARR_EL * 2u;
        const uint32_t Vs_l = Ks_h + 3u * KVARR_EL * 2u;

        float S[2][8][4];
#pragma unroll
        for (int mt = 0; mt < 2; mt++)
#pragma unroll
            for (int nt = 0; nt < 8; nt++)
#pragma unroll
                for (int r = 0; r < 4; r++) S[mt][nt][r] = 0.f;

        // ---- S = Q K^T: K frags shared across both m-tiles ----
#pragma unroll
        for (int ks = 0; ks < 4; ks++) {
            uint32_t kfh[4][4], kfl[4][4];
#pragma unroll
            for (int p = 0; p < 4; p++) {
                uint32_t off = (uint32_t)((p * 16 + b_n) * APITCH + ks * 16 + b_k) * 2u;
                LDM_X4(kfh[p][0], kfh[p][1], kfh[p][2], kfh[p][3], Ks_h + off);
                LDM_X4(kfl[p][0], kfl[p][1], kfl[p][2], kfl[p][3], Ks_l + off);
            }
            uint32_t qfh[2][4], qfl[2][4];
#pragma unroll
            for (int mt = 0; mt < 2; mt++) {
                uint32_t off = (uint32_t)((wm + mt * 16 + a_row) * APITCH + ks * 16 + a_k) * 2u;
                LDM_X4(qfh[mt][0], qfh[mt][1], qfh[mt][2], qfh[mt][3], Qh_u + off);
                LDM_X4(qfl[mt][0], qfl[mt][1], qfl[mt][2], qfl[mt][3], Ql_u + off);
            }
#pragma unroll
            for (int mt = 0; mt < 2; mt++)
#pragma unroll
                for (int nt = 0; nt < 8; nt++) {
                    int p = nt >> 1, o = (nt & 1) * 2;
                    MMA_BF16(S[mt][nt], qfh[mt], kfh[p][o], kfh[p][o+1]);
                }
#pragma unroll
            for (int mt = 0; mt < 2; mt++)
#pragma unroll
                for (int nt = 0; nt < 8; nt++) {
                    int p = nt >> 1, o = (nt & 1) * 2;
                    MMA_BF16(S[mt][nt], qfh[mt], kfl[p][o], kfl[p][o+1]);
                }
#pragma unroll
            for (int mt = 0; mt < 2; mt++)
#pragma unroll
                for (int nt = 0; nt < 8; nt++) {
                    int p = nt >> 1, o = (nt & 1) * 2;
                    MMA_BF16(S[mt][nt], qfl[mt], kfh[p][o], kfh[p][o+1]);
                }
        }

        // ---- online softmax per m-tile ----
#pragma unroll
        for (int mt = 0; mt < 2; mt++) {
            float mx0 = -1e30f, mx1 = -1e30f;
#pragma unroll
            for (int nt = 0; nt < 8; nt++) {
                mx0 = fmaxf(mx0, fmaxf(S[mt][nt][0], S[mt][nt][1]));
                mx1 = fmaxf(mx1, fmaxf(S[mt][nt][2], S[mt][nt][3]));
            }
            mx0 = fmaxf(mx0, __shfl_xor_sync(0xffffffffu, mx0, 1));
            mx0 = fmaxf(mx0, __shfl_xor_sync(0xffffffffu, mx0, 2));
            mx1 = fmaxf(mx1, __shfl_xor_sync(0xffffffffu, mx1, 1));
            mx1 = fmaxf(mx1, __shfl_xor_sync(0xffffffffu, mx1, 2));
            float mn0 = fmaxf(m_run[mt][0], mx0), mn1 = fmaxf(m_run[mt][1], mx1);
            float c0 = __expf(m_run[mt][0] - mn0), c1 = __expf(m_run[mt][1] - mn1);
            m_run[mt][0] = mn0; m_run[mt][1] = mn1;

            float s0 = 0.f, s1 = 0.f;
#pragma unroll
            for (int nt = 0; nt < 8; nt++) {
                S[mt][nt][0] = __expf(S[mt][nt][0] - mn0);
                S[mt][nt][1] = __expf(S[mt][nt][1] - mn0);
                S[mt][nt][2] = __expf(S[mt][nt][2] - mn1);
                S[mt][nt][3] = __expf(S[mt][nt][3] - mn1);
                s0 += S[mt][nt][0] + S[mt][nt][1];
                s1 += S[mt][nt][2] + S[mt][nt][3];
            }
            s0 += __shfl_xor_sync(0xffffffffu, s0, 1);
            s0 += __shfl_xor_sync(0xffffffffu, s0, 2);
            s1 += __shfl_xor_sync(0xffffffffu, s1, 1);
            s1 += __shfl_xor_sync(0xffffffffu, s1, 2);
            l_run[mt][0] = l_run[mt][0] * c0 + s0;
            l_run[mt][1] = l_run[mt][1] * c1 + s1;
#pragma unroll
            for (int d = 0; d < 8; d++) {
                O[mt][d][0] *= c0; O[mt][d][1] *= c0;
                O[mt][d][2] *= c1; O[mt][d][3] *= c1;
            }
        }

        // ---- O += P V: V frags shared across both m-tiles ----
#pragma unroll
        for (int ks = 0; ks < 4; ks++) {
            uint32_t pfh[2][4], pfl[2][4];
#pragma unroll
            for (int mt = 0; mt < 2; mt++) {
                bf16_split2(S[mt][2*ks][0],   S[mt][2*ks][1],   pfh[mt][0], pfl[mt][0]);
                bf16_split2(S[mt][2*ks][2],   S[mt][2*ks][3],   pfh[mt][1], pfl[mt][1]);
                bf16_split2(S[mt][2*ks+1][0], S[mt][2*ks+1][1], pfh[mt][2], pfl[mt][2]);
                bf16_split2(S[mt][2*ks+1][2], S[mt][2*ks+1][3], pfh[mt][3], pfl[mt][3]);
            }
            uint32_t vfh[4][4], vfl[4][4];
#pragma unroll
            for (int pd = 0; pd < 4; pd++) {
                uint32_t off = (uint32_t)((ks * 16 + (lane & 15)) * APITCH +
                                          pd * 16 + ((lane >> 4) << 3)) * 2u;
                LDM_X4T(vfh[pd][0], vfh[pd][1], vfh[pd][2], vfh[pd][3], Vs_h + off);
                LDM_X4T(vfl[pd][0], vfl[pd][1], vfl[pd][2], vfl[pd][3], Vs_l + off);
            }
#pragma unroll
            for (int mt = 0; mt < 2; mt++)
#pragma unroll
                for (int dt = 0; dt < 8; dt++) {
                    int pd = dt >> 1, o = (dt & 1) * 2;
                    MMA_BF16(O[mt][dt], pfh[mt], vfh[pd][o], vfh[pd][o+1]);
                }
#pragma unroll
            for (int mt = 0; mt < 2; mt++)
#pragma unroll
                for (int dt = 0; dt < 8; dt++) {
                    int pd = dt >> 1, o = (dt & 1) * 2;
                    MMA_BF16(O[mt][dt], pfh[mt], vfl[pd][o], vfl[pd][o+1]);
                }
#pragma unroll
            for (int mt = 0; mt < 2; mt++)
#pragma unroll
                for (int dt = 0; dt < 8; dt++) {
                    int pd = dt >> 1, o = (dt & 1) * 2;
                    MMA_BF16(O[mt][dt], pfl[mt], vfh[pd][o], vfh[pd][o+1]);
                }
        }

        __syncthreads();
        if (t + 2 < NT) issue(t + 2, t & 1);
    }

    // epilogue: bf16 hi/lo of O/l -> [b*s][h*64+d]
    const int g  = lane >> 2;
    const int t2 = (lane & 3) * 2;
    const int b  = bh >> 4;
    const int h  = bh & 15;
#pragma unroll
    for (int mt = 0; mt < 2; mt++) {
        float inv0 = 1.0f / l_run[mt][0], inv1 = 1.0f / l_run[mt][1];
        int row = b * SS + q0 + wm + mt * 16 + g;
#pragma unroll
        for (int dt = 0; dt < 8; dt++) {
            int col = h * HD + dt * 8 + t2;
            uint32_t hi, lo;
            bf16_split2(O[mt][dt][0] * inv0, O[mt][dt][1] * inv0, hi, lo);
            *reinterpret_cast<uint32_t*>(&aoh[(size_t)row * HID + col]) = hi;
            *reinterpret_cast<uint32_t*>(&aol[(size_t)row * HID + col]) = lo;
            bf16_split2(O[mt][dt][2] * inv1, O[mt][dt][3] * inv1, hi, lo);
            *reinterpret_cast<uint32_t*>(&aoh[(size_t)(row + 8) * HID + col]) = hi;
            *reinterpret_cast<uint32_t*>(&aol[(size_t)(row + 8) * HID + col]) = lo;
        }
    }
}

// ----------------------------------------------------------------------------
// Launch
// ----------------------------------------------------------------------------
extern "C" void kernel_launch(void* const* d_in, const int* in_sizes, int n_in,
                              void* d_out, int out_size)
{
    const float* x     = (const float*)d_in[0];
    const float* q_w   = (const float*)d_in[1];
    const float* q_b   = (const float*)d_in[2];
    const float* kv_w  = (const float*)d_in[3];
    const float* kv_b  = (const float*)d_in[4];
    const float* gq    = (const float*)d_in[5];
    const float* gk    = (const float*)d_in[6];
    const float* out_w = (const float*)d_in[7];
    float* out = (float*)d_out;

    __nv_bfloat16 *pqh, *pql, *pkh, *pkl, *pvh, *pvl;
    cudaGetSymbolAddress((void**)&pqh, g_qh);
    cudaGetSymbolAddress((void**)&pql, g_ql);
    cudaGetSymbolAddress((void**)&pkh, g_kh);
    cudaGetSymbolAddress((void**)&pkl, g_kl);
    cudaGetSymbolAddress((void**)&pvh, g_vh);
    cudaGetSymbolAddress((void**)&pvl, g_vl);
    __nv_bfloat16 *pxh, *pxl, *paoh, *paol, *pwh, *pwl, *powh, *powl;
    cudaGetSymbolAddress((void**)&pxh,  g_xh);
    cudaGetSymbolAddress((void**)&pxl,  g_xl);
    cudaGetSymbolAddress((void**)&paoh, g_aoh);
    cudaGetSymbolAddress((void**)&paol, g_aol);
    cudaGetSymbolAddress((void**)&pwh,  g_wh);
    cudaGetSymbolAddress((void**)&pwl,  g_wl);
    cudaGetSymbolAddress((void**)&powh, g_owh);
    cudaGetSymbolAddress((void**)&powl, g_owl);

    cudaFuncSetAttribute(attn_mma,
                         cudaFuncAttributeMaxDynamicSharedMemorySize, ATT_SMEM);

    // Pre-split inputs + all weights (one launch)
    split_all<<<(NSPLIT4 + 255) / 256, 256>>>(x, q_w, kv_w, out_w);

    // Merged QKV projection + fused qknorm/split/relayout
    {
        dim3 grid((3 * HID) / 128, MR / 128);   // (24, 64)
        gemm_qkv<<<grid, 256>>>(pxh, pxl, pwh, pwl, q_b, kv_b, gq, gk);
    }
    // Attention (tensor cores, 128 queries/CTA, 4 warps x 32 rows, 2 CTA/SM)
    {
        dim3 grid(SS / 128, BB * NH);           // (16, 64)
        attn_mma<<<grid, 128, ATT_SMEM>>>(pqh, pql, pkh, pkl, pvh, pvl, paoh, paol);
    }
    // Output projection
    {
        dim3 grid(HID / 128, MR / 128);
        gemm_pre<<<grid, 256>>>(paoh, paol, powh, powl, out, MR, HID, HID);
    }
}

// round 10
// speedup vs baseline: 1.1325x; 1.0197x over previous
#include <cuda_runtime.h>
#include <cuda_bf16.h>
#include <math.h>
#include <stdint.h>

// Problem constants
#define BB   4
#define SS   2048
#define HID  1024
#define NH   16
#define HD   64
#define MR   (BB*SS)   // 8192 rows

// Pre-split bf16 operands for attention, layout [b][h][s][64]
__device__ __nv_bfloat16 g_qh[(size_t)MR * HID];
__device__ __nv_bfloat16 g_ql[(size_t)MR * HID];
__device__ __nv_bfloat16 g_kh[(size_t)MR * HID];
__device__ __nv_bfloat16 g_kl[(size_t)MR * HID];
__device__ __nv_bfloat16 g_vh[(size_t)MR * HID];
__device__ __nv_bfloat16 g_vl[(size_t)MR * HID];
// Pre-split GEMM operands
__device__ __nv_bfloat16 g_xh [(size_t)MR * HID];
__device__ __nv_bfloat16 g_xl [(size_t)MR * HID];
__device__ __nv_bfloat16 g_aoh[(size_t)MR * HID];
__device__ __nv_bfloat16 g_aol[(size_t)MR * HID];
__device__ __nv_bfloat16 g_wh [(size_t)3 * HID * HID];   // concat(q_w, kv_w)
__device__ __nv_bfloat16 g_wl [(size_t)3 * HID * HID];
__device__ __nv_bfloat16 g_owh[(size_t)HID * HID];
__device__ __nv_bfloat16 g_owl[(size_t)HID * HID];

__device__ __forceinline__ uint32_t smem_u32(const void* p) {
    uint32_t a;
    asm("{ .reg .u64 t; cvta.to.shared.u64 t, %1; cvt.u32.u64 %0, t; }"
        : "=r"(a) : "l"(p));
    return a;
}

__device__ __forceinline__ void bf16_split2(float x, float y,
                                            uint32_t& hi, uint32_t& lo) {
    __nv_bfloat16 hx = __float2bfloat16(x);
    __nv_bfloat16 hy = __float2bfloat16(y);
    __nv_bfloat16 lx = __float2bfloat16(x - __bfloat162float(hx));
    __nv_bfloat16 ly = __float2bfloat16(y - __bfloat162float(hy));
    __nv_bfloat162 h; h.x = hx; h.y = hy;
    __nv_bfloat162 l; l.x = lx; l.y = ly;
    hi = *reinterpret_cast<uint32_t*>(&h);
    lo = *reinterpret_cast<uint32_t*>(&l);
}

#define LDM_X4(r0, r1, r2, r3, addr) \
    asm volatile("ldmatrix.sync.aligned.m8n8.x4.shared.b16 {%0,%1,%2,%3}, [%4];" \
                 : "=r"(r0), "=r"(r1), "=r"(r2), "=r"(r3) : "r"(addr))
#define LDM_X4T(r0, r1, r2, r3, addr) \
    asm volatile("ldmatrix.sync.aligned.m8n8.x4.trans.shared.b16 {%0,%1,%2,%3}, [%4];" \
                 : "=r"(r0), "=r"(r1), "=r"(r2), "=r"(r3) : "r"(addr))

#define MMA_BF16(d, a, b0v, b1v) \
    asm volatile("mma.sync.aligned.m16n8k16.row.col.f32.bf16.bf16.f32 " \
                 "{%0,%1,%2,%3}, {%4,%5,%6,%7}, {%8,%9}, {%0,%1,%2,%3};" \
                 : "+f"((d)[0]), "+f"((d)[1]), "+f"((d)[2]), "+f"((d)[3]) \
                 : "r"((a)[0]), "r"((a)[1]), "r"((a)[2]), "r"((a)[3]), \
                   "r"(b0v), "r"(b1v))

#define CP_ASYNC16(dst, src) \
    asm volatile("cp.async.cg.shared.global [%0], [%1], 16;" \
                 :: "r"(dst), "l"(src) : "memory")
#define CP_COMMIT() asm volatile("cp.async.commit_group;" ::: "memory")
#define CP_WAIT1()  asm volatile("cp.async.wait_group 1;" ::: "memory")
#define CP_WAIT0()  asm volatile("cp.async.wait_group 0;" ::: "memory")

// ============================================================================
// Merged split: fp32 -> bf16 hi/lo for x, q_w, kv_w, out_w in ONE launch
// ============================================================================
#define NX4   (MR * HID / 4)
#define NQW4  (HID * HID / 4)
#define NKVW4 (2 * HID * HID / 4)
#define NOW4  (HID * HID / 4)
#define NSPLIT4 (NX4 + NQW4 + NKVW4 + NOW4)

__global__ __launch_bounds__(256)
void split_all(const float* __restrict__ x, const float* __restrict__ qw,
               const float* __restrict__ kvw, const float* __restrict__ ow)
{
    int i = blockIdx.x * blockDim.x + threadIdx.x;
    if (i >= NSPLIT4) return;
    const float* src;
    __nv_bfloat16 *dh, *dl;
    int off;
    if (i < NX4) {
        src = x; dh = g_xh; dl = g_xl; off = i;
    } else if (i < NX4 + NQW4) {
        src = qw; dh = g_wh; dl = g_wl; off = i - NX4;
    } else if (i < NX4 + NQW4 + NKVW4) {
        src = kvw; off = i - NX4 - NQW4;
        dh = g_wh + (size_t)HID * HID; dl = g_wl + (size_t)HID * HID;
    } else {
        src = ow; dh = g_owh; dl = g_owl; off = i - NX4 - NQW4 - NKVW4;
    }
    float4 v = *reinterpret_cast<const float4*>(src + (size_t)off * 4);
    uint32_t h0, l0, h1, l1;
    bf16_split2(v.x, v.y, h0, l0);
    bf16_split2(v.z, v.w, h1, l1);
    *reinterpret_cast<uint2*>(dh + (size_t)off * 4) = make_uint2(h0, h1);
    *reinterpret_cast<uint2*>(dl + (size_t)off * 4) = make_uint2(l0, l1);
}

// ============================================================================
// Shared GEMM pieces: 4 warps/CTA, warp tile 64m x 64n, CTA tile 128x128.
// Per kk-16: 16 ldmatrix.x4 feed 96 MMAs (ratio 6, term pass = 32-deep ILP).
// ============================================================================
#define KC    32
#define PITCH 40
#define GT_EL (128 * PITCH)
#define GSTAGE_EL (4 * GT_EL)

#define GEMM_MAINLOOP64(acc)                                                      \
    for (int s = 0; s < NS; s++) {                                                \
        if (s < NS - 1) { CP_WAIT1(); } else { CP_WAIT0(); }                      \
        __syncthreads();                                                          \
        const uint32_t bAh = sb_u + (uint32_t)((s & 1) * GSTAGE_EL) * 2u;         \
        const uint32_t bAl = bAh + (uint32_t)GT_EL * 2u;                          \
        const uint32_t bBh = bAh + (uint32_t)(2 * GT_EL) * 2u;                    \
        const uint32_t bBl = bAh + (uint32_t)(3 * GT_EL) * 2u;                    \
        _Pragma("unroll")                                                         \
        for (int kk = 0; kk < KC; kk += 16) {                                     \
            uint32_t bh[16], bl[16];                                              \
            _Pragma("unroll")                                                     \
            for (int p = 0; p < 4; p++) {                                         \
                uint32_t off = (uint32_t)((wn + p * 16 + b_n) * PITCH + kk + b_k) * 2u; \
                LDM_X4(bh[p*4+0], bh[p*4+1], bh[p*4+2], bh[p*4+3], bBh + off);    \
                LDM_X4(bl[p*4+0], bl[p*4+1], bl[p*4+2], bl[p*4+3], bBl + off);    \
            }                                                                     \
            uint32_t ah[4][4], al[4][4];                                          \
            _Pragma("unroll")                                                     \
            for (int mt = 0; mt < 4; mt++) {                                      \
                uint32_t off = (uint32_t)((wm + mt * 16 + a_row) * PITCH + kk + a_k) * 2u; \
                LDM_X4(ah[mt][0], ah[mt][1], ah[mt][2], ah[mt][3], bAh + off);    \
                LDM_X4(al[mt][0], al[mt][1], al[mt][2], al[mt][3], bAl + off);    \
            }                                                                     \
            _Pragma("unroll")                                                     \
            for (int mt = 0; mt < 4; mt++)                                        \
                _Pragma("unroll")                                                 \
                for (int nt = 0; nt < 8; nt++) {                                  \
                    int p = nt >> 1, o = (nt & 1) * 2;                            \
                    MMA_BF16(acc[mt][nt], ah[mt], bh[p*4+o], bh[p*4+o+1]);        \
                }                                                                 \
            _Pragma("unroll")                                                     \
            for (int mt = 0; mt < 4; mt++)                                        \
                _Pragma("unroll")                                                 \
                for (int nt = 0; nt < 8; nt++) {                                  \
                    int p = nt >> 1, o = (nt & 1) * 2;                            \
                    MMA_BF16(acc[mt][nt], ah[mt], bl[p*4+o], bl[p*4+o+1]);        \
                }                                                                 \
            _Pragma("unroll")                                                     \
            for (int mt = 0; mt < 4; mt++)                                        \
                _Pragma("unroll")                                                 \
                for (int nt = 0; nt < 8; nt++) {                                  \
                    int p = nt >> 1, o = (nt & 1) * 2;                            \
                    MMA_BF16(acc[mt][nt], al[mt], bh[p*4+o], bh[p*4+o+1]);        \
                }                                                                 \
        }                                                                         \
        __syncthreads();                                                          \
        if (s + 2 < NS) issue(s + 2, s & 1);                                      \
    }

// issue one stage with 128 threads: 4 arrays x 512 16B-chunks
#define GEMM_ISSUE_DEF                                                            \
    auto issue = [&](int s, int bsel) {                                           \
        const int k0 = s * KC;                                                    \
        uint32_t base = sb_u + (uint32_t)bsel * GSTAGE_EL * 2u;                   \
        _Pragma("unroll")                                                         \
        for (int a = 0; a < 4; a++) {                                             \
            _Pragma("unroll")                                                     \
            for (int t = 0; t < 4; t++) {                                         \
                int idx = tid + t * 128;                                          \
                int r   = idx >> 2;                                               \
                int c   = (idx & 3) * 8;                                          \
                uint32_t dst = base + (uint32_t)(a * GT_EL + r * PITCH + c) * 2u; \
                CP_ASYNC16(dst, srcs[a] + (size_t)r * K + k0 + c);                \
            }                                                                     \
        }                                                                         \
        CP_COMMIT();                                                              \
    };

// ============================================================================
// Merged QKV GEMM + fused qknorm/split/relayout epilogue.
// Each warp owns a full 64-dim head slice -> norm is pure warp shuffles.
// ============================================================================
__global__ __launch_bounds__(128, 2)
void gemm_qkv(const __nv_bfloat16* __restrict__ Ah, const __nv_bfloat16* __restrict__ Al,
              const __nv_bfloat16* __restrict__ Wh, const __nv_bfloat16* __restrict__ Wl,
              const float* __restrict__ q_b, const float* __restrict__ kv_b,
              const float* __restrict__ gq, const float* __restrict__ gk)
{
    __shared__ __align__(16) __nv_bfloat16 sbuf[2 * GSTAGE_EL];

    const int K = HID;
    const int tid  = threadIdx.x;
    const int wid  = tid >> 5;
    const int lane = tid & 31;
    const int row0 = blockIdx.y * 128;
    const int col0 = blockIdx.x * 128;
    const int wm   = (wid >> 1) * 64;
    const int wn   = (wid & 1) * 64;

    const uint32_t sb_u = smem_u32(sbuf);
    const __nv_bfloat16* srcs[4] = {
        Ah + (size_t)row0 * K, Al + (size_t)row0 * K,
        Wh + (size_t)col0 * K, Wl + (size_t)col0 * K };

    const int NS = K / KC;
    GEMM_ISSUE_DEF

    issue(0, 0);
    issue(1, 1);

    const int a_row = lane & 15;
    const int a_k   = (lane >> 4) << 3;
    const int b_n   = (lane & 7) + ((lane >> 4) << 3);
    const int b_k   = lane & 8;

    float acc[4][8][4];
#pragma unroll
    for (int mt = 0; mt < 4; mt++)
#pragma unroll
        for (int nt = 0; nt < 8; nt++)
#pragma unroll
            for (int r = 0; r < 4; r++) acc[mt][nt][r] = 0.f;

    GEMM_MAINLOOP64(acc)

    // ---- fused epilogue (one head per warp-column) ----
    const int g  = lane >> 2;
    const int t2 = (lane & 3) * 2;

    // bias add (before norm, per reference)
#pragma unroll
    for (int nt = 0; nt < 8; nt++) {
        int col = col0 + wn + nt * 8 + t2;
        float b0 = (col < HID) ? __ldg(&q_b[col])     : __ldg(&kv_b[col - HID]);
        float b1 = (col + 1 < HID) ? __ldg(&q_b[col + 1]) : __ldg(&kv_b[col + 1 - HID]);
#pragma unroll
        for (int mt = 0; mt < 4; mt++) {
            acc[mt][nt][0] += b0; acc[mt][nt][1] += b1;
            acc[mt][nt][2] += b0; acc[mt][nt][3] += b1;
        }
    }

    const int seg = (col0 < HID) ? 0 : (col0 < 2 * HID) ? 1 : 2;
    const int h   = ((col0 & (HID - 1)) + wn) >> 6;
    __nv_bfloat16* dh = (seg == 0) ? g_qh : (seg == 1) ? g_kh : g_vh;
    __nv_bfloat16* dl = (seg == 0) ? g_ql : (seg == 1) ? g_kl : g_vl;
    const float* gamma = (seg == 0) ? gq : gk;

#pragma unroll
    for (int mt = 0; mt < 4; mt++) {
#pragma unroll
        for (int rh = 0; rh < 2; rh++) {
            float inv = 1.0f;
            if (seg < 2) {
                float ssum = 0.f;
#pragma unroll
                for (int nt = 0; nt < 8; nt++) {
                    float v0 = acc[mt][nt][rh * 2 + 0];
                    float v1 = acc[mt][nt][rh * 2 + 1];
                    ssum += v0 * v0 + v1 * v1;
                }
                ssum += __shfl_xor_sync(0xffffffffu, ssum, 1);
                ssum += __shfl_xor_sync(0xffffffffu, ssum, 2);
                inv = 8.0f / fmaxf(sqrtf(ssum), 1e-12f);
            }
            int row  = row0 + wm + mt * 16 + g + rh * 8;
            int b    = row >> 11;
            int srow = row & (SS - 1);
            size_t base = ((size_t)(b * NH + h) * SS + srow) * HD;
#pragma unroll
            for (int nt = 0; nt < 8; nt++) {
                int d = nt * 8 + t2;
                float g0 = 1.f, g1 = 1.f;
                if (seg < 2) {
                    g0 = __ldg(&gamma[h * HD + d]);
                    g1 = __ldg(&gamma[h * HD + d + 1]);
                }
                float v0 = acc[mt][nt][rh * 2 + 0] * inv * g0;
                float v1 = acc[mt][nt][rh * 2 + 1] * inv * g1;
                uint32_t hi, lo;
                bf16_split2(v0, v1, hi, lo);
                *reinterpret_cast<uint32_t*>(&dh[base + d]) = hi;
                *reinterpret_cast<uint32_t*>(&dl[base + d]) = lo;
            }
        }
    }
}

// ============================================================================
// Out-proj GEMM (fp32 out), 4 warps, 64x64 warp tile.
// ============================================================================
__global__ __launch_bounds__(128, 2)
void gemm_pre(const __nv_bfloat16* __restrict__ Ah, const __nv_bfloat16* __restrict__ Al,
              const __nv_bfloat16* __restrict__ Wh, const __nv_bfloat16* __restrict__ Wl,
              float* __restrict__ C, int M, int N, int K)
{
    __shared__ __align__(16) __nv_bfloat16 sbuf[2 * GSTAGE_EL];

    const int tid  = threadIdx.x;
    const int wid  = tid >> 5;
    const int lane = tid & 31;
    const int row0 = blockIdx.y * 128;
    const int col0 = blockIdx.x * 128;
    const int wm   = (wid >> 1) * 64;
    const int wn   = (wid & 1) * 64;

    const uint32_t sb_u = smem_u32(sbuf);
    const __nv_bfloat16* srcs[4] = {
        Ah + (size_t)row0 * K, Al + (size_t)row0 * K,
        Wh + (size_t)col0 * K, Wl + (size_t)col0 * K };

    const int NS = K / KC;
    GEMM_ISSUE_DEF

    issue(0, 0);
    issue(1, 1);

    const int a_row = lane & 15;
    const int a_k   = (lane >> 4) << 3;
    const int b_n   = (lane & 7) + ((lane >> 4) << 3);
    const int b_k   = lane & 8;

    float acc[4][8][4];
#pragma unroll
    for (int mt = 0; mt < 4; mt++)
#pragma unroll
        for (int nt = 0; nt < 8; nt++)
#pragma unroll
            for (int r = 0; r < 4; r++) acc[mt][nt][r] = 0.f;

    GEMM_MAINLOOP64(acc)

    const int g  = lane >> 2;
    const int t2 = (lane & 3) * 2;
#pragma unroll
    for (int mt = 0; mt < 4; mt++) {
#pragma unroll
        for (int nt = 0; nt < 8; nt++) {
            int row = row0 + wm + mt * 16 + g;
            int col = col0 + wn + nt * 8 + t2;
            *reinterpret_cast<float2*>(&C[(size_t)row * N + col]) =
                make_float2(acc[mt][nt][0], acc[mt][nt][1]);
            *reinterpret_cast<float2*>(&C[(size_t)(row + 8) * N + col]) =
                make_float2(acc[mt][nt][2], acc[mt][nt][3]);
        }
    }
}

// ============================================================================
// Tensor-core flash attention: 4 warps x 32 query rows (round-9 proven).
// ============================================================================
#define APITCH 72
#define QTILE_EL  (128 * APITCH)
#define KVARR_EL  (64 * APITCH)
#define BUF_EL    (4 * KVARR_EL)
#define ATT_SMEM  ((2 * QTILE_EL + 2 * BUF_EL) * 2)   // 110592 bytes
#define NT        (SS / 64)

__global__ __launch_bounds__(128, 2)
void attn_mma(const __nv_bfloat16* __restrict__ qh, const __nv_bfloat16* __restrict__ ql,
              const __nv_bfloat16* __restrict__ kh, const __nv_bfloat16* __restrict__ kl,
              const __nv_bfloat16* __restrict__ vh, const __nv_bfloat16* __restrict__ vl,
              __nv_bfloat16* __restrict__ aoh, __nv_bfloat16* __restrict__ aol)
{
    extern __shared__ __nv_bfloat16 sm[];
    __nv_bfloat16* Qh = sm;
    __nv_bfloat16* Ql = Qh + QTILE_EL;
    __nv_bfloat16* Bf = Ql + QTILE_EL;

    const int tid  = threadIdx.x;
    const int wid  = tid >> 5;
    const int lane = tid & 31;
    const int bh   = blockIdx.y;
    const int q0   = blockIdx.x * 128;
    const int wm   = wid * 32;
    const size_t bh_off = (size_t)bh * SS * HD;

    const __nv_bfloat16* srcs[4] = {kh + bh_off, kl + bh_off, vh + bh_off, vl + bh_off};
    const uint32_t buf_u[2] = { smem_u32(Bf), smem_u32(Bf + BUF_EL) };
    const uint32_t Qh_u = smem_u32(Qh);
    const uint32_t Ql_u = smem_u32(Ql);

    auto issue = [&](int kt, int bsel) {
#pragma unroll
        for (int i = 0; i < 16; i++) {
            const __nv_bfloat16* sp = srcs[i >> 2];
            int rem = ((i & 3) << 7) + tid;
            int r = rem >> 3;
            int c = (rem & 7) * 8;
            uint32_t dst = buf_u[bsel] + (uint32_t)((i >> 2) * KVARR_EL + r * APITCH + c) * 2u;
            CP_ASYNC16(dst, sp + (size_t)(kt * 64 + r) * HD + c);
        }
        CP_COMMIT();
    };

    issue(0, 0);
    issue(1, 1);

    {
        const __nv_bfloat16* qsrc[2] = {qh + bh_off, ql + bh_off};
        __nv_bfloat16* qdst[2] = {Qh, Ql};
#pragma unroll
        for (int i = 0; i < 16; i++) {
            int rem = ((i & 7) << 7) + tid;
            int r = rem >> 3;
            int c = (rem & 7) * 8;
            uint4 v = *reinterpret_cast<const uint4*>(
                qsrc[i >> 3] + (size_t)(q0 + r) * HD + c);
            *reinterpret_cast<uint4*>(qdst[i >> 3] + r * APITCH + c) = v;
        }
    }
    __syncthreads();

    const int a_row = lane & 15;
    const int a_k   = (lane >> 4) << 3;
    const int b_n   = (lane & 7) + ((lane >> 4) << 3);
    const int b_k   = lane & 8;

    float m_run[2][2], l_run[2][2];
    float O[2][8][4];
#pragma unroll
    for (int mt = 0; mt < 2; mt++) {
        m_run[mt][0] = -1e30f; m_run[mt][1] = -1e30f;
        l_run[mt][0] = 0.f;    l_run[mt][1] = 0.f;
#pragma unroll
        for (int d = 0; d < 8; d++)
#pragma unroll
            for (int r = 0; r < 4; r++) O[mt][d][r] = 0.f;
    }

    for (int t = 0; t < NT; t++) {
        if (t < NT - 1) { CP_WAIT1(); } else { CP_WAIT0(); }
        __syncthreads();

        const uint32_t Ks_h = buf_u[t & 1];
        const uint32_t Ks_l = Ks_h + KVARR_EL * 2u;
        const uint32_t Vs_h = Ks_h + 2u * KVARR_EL * 2u;
        const uint32_t Vs_l = Ks_h + 3u * KVARR_EL * 2u;

        float S[2][8][4];
#pragma unroll
        for (int mt = 0; mt < 2; mt++)
#pragma unroll
            for (int nt = 0; nt < 8; nt++)
#pragma unroll
                for (int r = 0; r < 4; r++) S[mt][nt][r] = 0.f;

#pragma unroll
        for (int ks = 0; ks < 4; ks++) {
            uint32_t kfh[4][4], kfl[4][4];
#pragma unroll
            for (int p = 0; p < 4; p++) {
                uint32_t off = (uint32_t)((p * 16 + b_n) * APITCH + ks * 16 + b_k) * 2u;
                LDM_X4(kfh[p][0], kfh[p][1], kfh[p][2], kfh[p][3], Ks_h + off);
                LDM_X4(kfl[p][0], kfl[p][1], kfl[p][2], kfl[p][3], Ks_l + off);
            }
            uint32_t qfh[2][4], qfl[2][4];
#pragma unroll
            for (int mt = 0; mt < 2; mt++) {
                uint32_t off = (uint32_t)((wm + mt * 16 + a_row) * APITCH + ks * 16 + a_k) * 2u;
                LDM_X4(qfh[mt][0], qfh[mt][1], qfh[mt][2], qfh[mt][3], Qh_u + off);
                LDM_X4(qfl[mt][0], qfl[mt][1], qfl[mt][2], qfl[mt][3], Ql_u + off);
            }
#pragma unroll
            for (int mt = 0; mt < 2; mt++)
#pragma unroll
                for (int nt = 0; nt < 8; nt++) {
                    int p = nt >> 1, o = (nt & 1) * 2;
                    MMA_BF16(S[mt][nt], qfh[mt], kfh[p][o], kfh[p][o+1]);
                }
#pragma unroll
            for (int mt = 0; mt < 2; mt++)
#pragma unroll
                for (int nt = 0; nt < 8; nt++) {
                    int p = nt >> 1, o = (nt & 1) * 2;
                    MMA_BF16(S[mt][nt], qfh[mt], kfl[p][o], kfl[p][o+1]);
                }
#pragma unroll
            for (int mt = 0; mt < 2; mt++)
#pragma unroll
                for (int nt = 0; nt < 8; nt++) {
                    int p = nt >> 1, o = (nt & 1) * 2;
                    MMA_BF16(S[mt][nt], qfl[mt], kfh[p][o], kfh[p][o+1]);
                }
        }

#pragma unroll
        for (int mt = 0; mt < 2; mt++) {
            float mx0 = -1e30f, mx1 = -1e30f;
#pragma unroll
            for (int nt = 0; nt < 8; nt++) {
                mx0 = fmaxf(mx0, fmaxf(S[mt][nt][0], S[mt][nt][1]));
                mx1 = fmaxf(mx1, fmaxf(S[mt][nt][2], S[mt][nt][3]));
            }
            mx0 = fmaxf(mx0, __shfl_xor_sync(0xffffffffu, mx0, 1));
            mx0 = fmaxf(mx0, __shfl_xor_sync(0xffffffffu, mx0, 2));
            mx1 = fmaxf(mx1, __shfl_xor_sync(0xffffffffu, mx1, 1));
            mx1 = fmaxf(mx1, __shfl_xor_sync(0xffffffffu, mx1, 2));
            float mn0 = fmaxf(m_run[mt][0], mx0), mn1 = fmaxf(m_run[mt][1], mx1);
            float c0 = __expf(m_run[mt][0] - mn0), c1 = __expf(m_run[mt][1] - mn1);
            m_run[mt][0] = mn0; m_run[mt][1] = mn1;

            float s0 = 0.f, s1 = 0.f;
#pragma unroll
            for (int nt = 0; nt < 8; nt++) {
                S[mt][nt][0] = __expf(S[mt][nt][0] - mn0);
                S[mt][nt][1] = __expf(S[mt][nt][1] - mn0);
                S[mt][nt][2] = __expf(S[mt][nt][2] - mn1);
                S[mt][nt][3] = __expf(S[mt][nt][3] - mn1);
                s0 += S[mt][nt][0] + S[mt][nt][1];
                s1 += S[mt][nt][2] + S[mt][nt][3];
            }
            s0 += __shfl_xor_sync(0xffffffffu, s0, 1);
            s0 += __shfl_xor_sync(0xffffffffu, s0, 2);
            s1 += __shfl_xor_sync(0xffffffffu, s1, 1);
            s1 += __shfl_xor_sync(0xffffffffu, s1, 2);
            l_run[mt][0] = l_run[mt][0] * c0 + s0;
            l_run[mt][1] = l_run[mt][1] * c1 + s1;
#pragma unroll
            for (int d = 0; d < 8; d++) {
                O[mt][d][0] *= c0; O[mt][d][1] *= c0;
                O[mt][d][2] *= c1; O[mt][d][3] *= c1;
            }
        }

#pragma unroll
        for (int ks = 0; ks < 4; ks++) {
            uint32_t pfh[2][4], pfl[2][4];
#pragma unroll
            for (int mt = 0; mt < 2; mt++) {
                bf16_split2(S[mt][2*ks][0],   S[mt][2*ks][1],   pfh[mt][0], pfl[mt][0]);
                bf16_split2(S[mt][2*ks][2],   S[mt][2*ks][3],   pfh[mt][1], pfl[mt][1]);
                bf16_split2(S[mt][2*ks+1][0], S[mt][2*ks+1][1], pfh[mt][2], pfl[mt][2]);
                bf16_split2(S[mt][2*ks+1][2], S[mt][2*ks+1][3], pfh[mt][3], pfl[mt][3]);
            }
            uint32_t vfh[4][4], vfl[4][4];
#pragma unroll
            for (int pd = 0; pd < 4; pd++) {
                uint32_t off = (uint32_t)((ks * 16 + (lane & 15)) * APITCH +
                                          pd * 16 + ((lane >> 4) << 3)) * 2u;
                LDM_X4T(vfh[pd][0], vfh[pd][1], vfh[pd][2], vfh[pd][3], Vs_h + off);
                LDM_X4T(vfl[pd][0], vfl[pd][1], vfl[pd][2], vfl[pd][3], Vs_l + off);
            }
#pragma unroll
            for (int mt = 0; mt < 2; mt++)
#pragma unroll
                for (int dt = 0; dt < 8; dt++) {
                    int pd = dt >> 1, o = (dt & 1) * 2;
                    MMA_BF16(O[mt][dt], pfh[mt], vfh[pd][o], vfh[pd][o+1]);
                }
#pragma unroll
            for (int mt = 0; mt < 2; mt++)
#pragma unroll
                for (int dt = 0; dt < 8; dt++) {
                    int pd = dt >> 1, o = (dt & 1) * 2;
                    MMA_BF16(O[mt][dt], pfh[mt], vfl[pd][o], vfl[pd][o+1]);
                }
#pragma unroll
            for (int mt = 0; mt < 2; mt++)
#pragma unroll
                for (int dt = 0; dt < 8; dt++) {
                    int pd = dt >> 1, o = (dt & 1) * 2;
                    MMA_BF16(O[mt][dt], pfl[mt], vfh[pd][o], vfh[pd][o+1]);
                }
        }

        __syncthreads();
        if (t + 2 < NT) issue(t + 2, t & 1);
    }

    const int g  = lane >> 2;
    const int t2 = (lane & 3) * 2;
    const int b  = bh >> 4;
    const int h  = bh & 15;
#pragma unroll
    for (int mt = 0; mt < 2; mt++) {
        float inv0 = 1.0f / l_run[mt][0], inv1 = 1.0f / l_run[mt][1];
        int row = b * SS + q0 + wm + mt * 16 + g;
#pragma unroll
        for (int dt = 0; dt < 8; dt++) {
            int col = h * HD + dt * 8 + t2;
            uint32_t hi, lo;
            bf16_split2(O[mt][dt][0] * inv0, O[mt][dt][1] * inv0, hi, lo);
            *reinterpret_cast<uint32_t*>(&aoh[(size_t)row * HID + col]) = hi;
            *reinterpret_cast<uint32_t*>(&aol[(size_t)row * HID + col]) = lo;
            bf16_split2(O[mt][dt][2] * inv1, O[mt][dt][3] * inv1, hi, lo);
            *reinterpret_cast<uint32_t*>(&aoh[(size_t)(row + 8) * HID + col]) = hi;
            *reinterpret_cast<uint32_t*>(&aol[(size_t)(row + 8) * HID + col]) = lo;
        }
    }
}

// ----------------------------------------------------------------------------
// Launch
// ----------------------------------------------------------------------------
extern "C" void kernel_launch(void* const* d_in, const int* in_sizes, int n_in,
                              void* d_out, int out_size)
{
    const float* x     = (const float*)d_in[0];
    const float* q_w   = (const float*)d_in[1];
    const float* q_b   = (const float*)d_in[2];
    const float* kv_w  = (const float*)d_in[3];
    const float* kv_b  = (const float*)d_in[4];
    const float* gq    = (const float*)d_in[5];
    const float* gk    = (const float*)d_in[6];
    const float* out_w = (const float*)d_in[7];
    float* out = (float*)d_out;

    __nv_bfloat16 *pqh, *pql, *pkh, *pkl, *pvh, *pvl;
    cudaGetSymbolAddress((void**)&pqh, g_qh);
    cudaGetSymbolAddress((void**)&pql, g_ql);
    cudaGetSymbolAddress((void**)&pkh, g_kh);
    cudaGetSymbolAddress((void**)&pkl, g_kl);
    cudaGetSymbolAddress((void**)&pvh, g_vh);
    cudaGetSymbolAddress((void**)&pvl, g_vl);
    __nv_bfloat16 *pxh, *pxl, *paoh, *paol, *pwh, *pwl, *powh, *powl;
    cudaGetSymbolAddress((void**)&pxh,  g_xh);
    cudaGetSymbolAddress((void**)&pxl,  g_xl);
    cudaGetSymbolAddress((void**)&paoh, g_aoh);
    cudaGetSymbolAddress((void**)&paol, g_aol);
    cudaGetSymbolAddress((void**)&pwh,  g_wh);
    cudaGetSymbolAddress((void**)&pwl,  g_wl);
    cudaGetSymbolAddress((void**)&powh, g_owh);
    cudaGetSymbolAddress((void**)&powl, g_owl);

    cudaFuncSetAttribute(attn_mma,
                         cudaFuncAttributeMaxDynamicSharedMemorySize, ATT_SMEM);

    // Pre-split inputs + all weights (one launch)
    split_all<<<(NSPLIT4 + 255) / 256, 256>>>(x, q_w, kv_w, out_w);

    // Merged QKV projection + fused qknorm/split/relayout (4 warps/CTA)
    {
        dim3 grid((3 * HID) / 128, MR / 128);   // (24, 64)
        gemm_qkv<<<grid, 128>>>(pxh, pxl, pwh, pwl, q_b, kv_b, gq, gk);
    }
    // Attention (tensor cores, 128 queries/CTA, 4 warps x 32 rows, 2 CTA/SM)
    {
        dim3 grid(SS / 128, BB * NH);           // (16, 64)
        attn_mma<<<grid, 128, ATT_SMEM>>>(pqh, pql, pkh, pkl, pvh, pvl, paoh, paol);
    }
    // Output projection (4 warps/CTA)
    {
        dim3 grid(HID / 128, MR / 128);
        gemm_pre<<<grid, 128>>>(paoh, paol, powh, powl, out, MR, HID, HID);
    }
}